// round 1
// baseline (speedup 1.0000x reference)
#include <cuda_runtime.h>
#include <cuda_bf16.h>
#include <math.h>

// Problem constants
#define BB   4
#define MM   2048
#define DD   256
#define EE   1024
#define HH   8
#define DH   32
#define TD   768   // 3*DD

// ---------------------------------------------------------------------------
// Scratch (no cudaMalloc allowed)
// ---------------------------------------------------------------------------
__device__ float g_qkv  [BB * MM * TD];   // 24 MB
__device__ float g_attn [BB * MM * DD];   // 8 MB  (attention output, pre out-proj)
__device__ float g_attnp[BB * MM * DD];   // 8 MB  (after out-proj)
__device__ float g_S    [BB * EE * DD];   // 4 MB
__device__ float g_ef   [BB * EE * DD];   // 4 MB  (S * softmax_e(S))
__device__ float g_ef2  [BB * EE * DD];   // 4 MB  (after proj_w)

// ---------------------------------------------------------------------------
// Generic SGEMM: C[M,N] = A[M,K] @ B[N,K]^T + bias   (row-major, weights NT)
// BM=BN=64, BK=16, 256 threads, 4x4 per-thread tile.
// Requires M%64==0, N%64==0, K%16==0.
// ---------------------------------------------------------------------------
__global__ __launch_bounds__(256) void sgemm_nt(
    const float* __restrict__ A, const float* __restrict__ B,
    const float* __restrict__ bias, float* __restrict__ C,
    int M, int N, int K)
{
    __shared__ float As[16][68];
    __shared__ float Bs[16][68];
    const int tid = threadIdx.x;
    const int tx = tid & 15, ty = tid >> 4;
    const int m0 = blockIdx.y * 64, n0 = blockIdx.x * 64;

    float acc[4][4] = {};

    for (int k0 = 0; k0 < K; k0 += 16) {
        // load: each thread one float4 of A and one of B (transposed store)
        const int r  = tid >> 2;        // 0..63
        const int kc = (tid & 3) * 4;   // 0,4,8,12
        float4 va = *(const float4*)&A[(size_t)(m0 + r) * K + k0 + kc];
        float4 vb = *(const float4*)&B[(size_t)(n0 + r) * K + k0 + kc];
        As[kc + 0][r] = va.x; As[kc + 1][r] = va.y; As[kc + 2][r] = va.z; As[kc + 3][r] = va.w;
        Bs[kc + 0][r] = vb.x; Bs[kc + 1][r] = vb.y; Bs[kc + 2][r] = vb.z; Bs[kc + 3][r] = vb.w;
        __syncthreads();

        #pragma unroll
        for (int k = 0; k < 16; k++) {
            float4 a  = *(const float4*)&As[k][ty * 4];
            float4 b4 = *(const float4*)&Bs[k][tx * 4];
            acc[0][0] += a.x * b4.x; acc[0][1] += a.x * b4.y; acc[0][2] += a.x * b4.z; acc[0][3] += a.x * b4.w;
            acc[1][0] += a.y * b4.x; acc[1][1] += a.y * b4.y; acc[1][2] += a.y * b4.z; acc[1][3] += a.y * b4.w;
            acc[2][0] += a.z * b4.x; acc[2][1] += a.z * b4.y; acc[2][2] += a.z * b4.z; acc[2][3] += a.z * b4.w;
            acc[3][0] += a.w * b4.x; acc[3][1] += a.w * b4.y; acc[3][2] += a.w * b4.z; acc[3][3] += a.w * b4.w;
        }
        __syncthreads();
    }

    #pragma unroll
    for (int i = 0; i < 4; i++) {
        #pragma unroll
        for (int j = 0; j < 4; j++) {
            int n = n0 + tx * 4 + j;
            float v = acc[i][j] + (bias ? bias[n] : 0.0f);
            C[(size_t)(m0 + ty * 4 + i) * N + n] = v;
        }
    }
}

// ---------------------------------------------------------------------------
// TN GEMM for S = inc^T @ attnp, per batch:
//   S[b,e,d] = sum_m inc[b,m,e] * attnp[b,m,d]
// A = inc[b] is [K=2048, E] (lda=EE); B = attnp[b] is [K=2048, D] (ldb=DD).
// grid (E/64, D/64, BB)
// ---------------------------------------------------------------------------
__global__ __launch_bounds__(256) void sgemm_tn_S(
    const float* __restrict__ inc, const float* __restrict__ attn,
    float* __restrict__ S)
{
    const int b  = blockIdx.z;
    const int e0 = blockIdx.x * 64, d0 = blockIdx.y * 64;
    const float* A  = inc  + (size_t)b * MM * EE;
    const float* Bm = attn + (size_t)b * MM * DD;

    __shared__ float As[16][68];
    __shared__ float Bs[16][68];
    const int tid = threadIdx.x;
    const int tx = tid & 15, ty = tid >> 4;

    float acc[4][4] = {};

    for (int k0 = 0; k0 < MM; k0 += 16) {
        const int kr = tid >> 4;        // 0..15
        const int ec = (tid & 15) * 4;  // 0..60
        *(float4*)&As[kr][ec] = *(const float4*)&A [(size_t)(k0 + kr) * EE + e0 + ec];
        *(float4*)&Bs[kr][ec] = *(const float4*)&Bm[(size_t)(k0 + kr) * DD + d0 + ec];
        __syncthreads();

        #pragma unroll
        for (int k = 0; k < 16; k++) {
            float4 a  = *(const float4*)&As[k][ty * 4];
            float4 b4 = *(const float4*)&Bs[k][tx * 4];
            acc[0][0] += a.x * b4.x; acc[0][1] += a.x * b4.y; acc[0][2] += a.x * b4.z; acc[0][3] += a.x * b4.w;
            acc[1][0] += a.y * b4.x; acc[1][1] += a.y * b4.y; acc[1][2] += a.y * b4.z; acc[1][3] += a.y * b4.w;
            acc[2][0] += a.z * b4.x; acc[2][1] += a.z * b4.y; acc[2][2] += a.z * b4.z; acc[2][3] += a.z * b4.w;
            acc[3][0] += a.w * b4.x; acc[3][1] += a.w * b4.y; acc[3][2] += a.w * b4.z; acc[3][3] += a.w * b4.w;
        }
        __syncthreads();
    }

    float* Sb = S + (size_t)b * EE * DD;
    #pragma unroll
    for (int i = 0; i < 4; i++)
        #pragma unroll
        for (int j = 0; j < 4; j++)
            Sb[(size_t)(e0 + ty * 4 + i) * DD + d0 + tx * 4 + j] = acc[i][j];
}

// ---------------------------------------------------------------------------
// Flash attention, fp32. One block = 64 query rows of one (b,h).
// Online softmax; P staged through SMEM for the PV GEMM.
// grid (MM/64 = 32, BB*HH = 32), 256 threads (tx 0..15, ty 0..15).
// Per-thread: S tile 4x4, O tile 4 rows x 2 dh-cols.
// ---------------------------------------------------------------------------
__global__ __launch_bounds__(256) void flash_attn(
    const float* __restrict__ qkv, float* __restrict__ o)
{
    const int bh = blockIdx.y;
    const int b = bh >> 3, h = bh & 7;
    const int m0 = blockIdx.x * 64;
    const int tid = threadIdx.x;
    const int tx = tid & 15, ty = tid >> 4;

    __shared__ float Qs[32 * 68];     // [k][m], padded
    __shared__ float Ks[32 * 68];     // [k][j]
    __shared__ float Vs[64 * 34];     // [j][c]
    __shared__ float Ps[64 * 64];     // [row][j]
    __shared__ float red[64 * 16];
    __shared__ float mi[64], li[64], a_s[64];

    const float scale = 0.1767766952966369f; // 1/sqrt(32)
    const size_t baseQ = (size_t)(b * MM) * TD + h * DH;

    for (int i = tid; i < 64 * 32; i += 256) {
        int r = i >> 5, k = i & 31;
        Qs[k * 68 + r] = qkv[baseQ + (size_t)(m0 + r) * TD + k] * scale;
    }
    if (tid < 64) { mi[tid] = -1e30f; li[tid] = 0.0f; }
    float O[4][2] = {};
    __syncthreads();

    for (int kt = 0; kt < MM; kt += 64) {
        // load K, V tiles
        for (int i = tid; i < 64 * 32; i += 256) {
            int j = i >> 5, k = i & 31;
            const float* kp = qkv + baseQ + (size_t)(kt + j) * TD;
            Ks[k * 68 + j] = kp[256 + k];
            Vs[j * 34 + k] = kp[512 + k];
        }
        __syncthreads();

        // S = Q @ K^T  (4x4 per thread)
        float acc[4][4] = {};
        #pragma unroll
        for (int k = 0; k < 32; k++) {
            float4 a  = *(const float4*)&Qs[k * 68 + ty * 4];
            float4 b4 = *(const float4*)&Ks[k * 68 + tx * 4];
            acc[0][0] += a.x * b4.x; acc[0][1] += a.x * b4.y; acc[0][2] += a.x * b4.z; acc[0][3] += a.x * b4.w;
            acc[1][0] += a.y * b4.x; acc[1][1] += a.y * b4.y; acc[1][2] += a.y * b4.z; acc[1][3] += a.y * b4.w;
            acc[2][0] += a.z * b4.x; acc[2][1] += a.z * b4.y; acc[2][2] += a.z * b4.z; acc[2][3] += a.z * b4.w;
            acc[3][0] += a.w * b4.x; acc[3][1] += a.w * b4.y; acc[3][2] += a.w * b4.z; acc[3][3] += a.w * b4.w;
        }

        // per-thread row-max partials
        #pragma unroll
        for (int i = 0; i < 4; i++) {
            float rm = fmaxf(fmaxf(acc[i][0], acc[i][1]), fmaxf(acc[i][2], acc[i][3]));
            red[(ty * 4 + i) * 16 + tx] = rm;
        }
        __syncthreads();
        if (tid < 64) {
            float t = red[tid * 16];
            #pragma unroll
            for (int q = 1; q < 16; q++) t = fmaxf(t, red[tid * 16 + q]);
            float mold = mi[tid];
            float mnew = fmaxf(mold, t);
            a_s[tid] = __expf(mold - mnew);
            mi[tid]  = mnew;
        }
        __syncthreads();

        // exponentiate, stage P, partial row sums, rescale O
        #pragma unroll
        for (int i = 0; i < 4; i++) {
            int row = ty * 4 + i;
            float mnew = mi[row];
            float s = 0.0f;
            #pragma unroll
            for (int j = 0; j < 4; j++) {
                float p = __expf(acc[i][j] - mnew);
                acc[i][j] = p; s += p;
            }
            *(float4*)&Ps[row * 64 + tx * 4] =
                make_float4(acc[i][0], acc[i][1], acc[i][2], acc[i][3]);
            red[row * 16 + tx] = s;
            float al = a_s[row];
            O[i][0] *= al; O[i][1] *= al;
        }
        __syncthreads();

        if (tid < 64) {
            float s = 0.0f;
            #pragma unroll
            for (int q = 0; q < 16; q++) s += red[tid * 16 + q];
            li[tid] = li[tid] * a_s[tid] + s;
        }

        // O += P @ V
        #pragma unroll
        for (int jj = 0; jj < 64; jj += 4) {
            float2 v0 = *(const float2*)&Vs[(jj + 0) * 34 + tx * 2];
            float2 v1 = *(const float2*)&Vs[(jj + 1) * 34 + tx * 2];
            float2 v2 = *(const float2*)&Vs[(jj + 2) * 34 + tx * 2];
            float2 v3 = *(const float2*)&Vs[(jj + 3) * 34 + tx * 2];
            #pragma unroll
            for (int i = 0; i < 4; i++) {
                float4 p = *(const float4*)&Ps[(ty * 4 + i) * 64 + jj];
                O[i][0] += p.x * v0.x + p.y * v1.x + p.z * v2.x + p.w * v3.x;
                O[i][1] += p.x * v0.y + p.y * v1.y + p.z * v2.y + p.w * v3.y;
            }
        }
        __syncthreads();
    }

    #pragma unroll
    for (int i = 0; i < 4; i++) {
        int row = ty * 4 + i;
        float inv = 1.0f / li[row];
        size_t off = ((size_t)(b * MM + m0 + row)) * DD + h * DH + tx * 2;
        o[off]     = O[i][0] * inv;
        o[off + 1] = O[i][1] * inv;
    }
}

// ---------------------------------------------------------------------------
// Column softmax over e (dim of size 1024) + multiply:  ef = S * softmax_e(S)
// grid (DD/64, BB); 256 threads = 64 d-cols x 4 row-groups. 3 passes over L2.
// ---------------------------------------------------------------------------
__global__ __launch_bounds__(256) void col_softmax_mul(
    const float* __restrict__ S, float* __restrict__ ef)
{
    const int b  = blockIdx.y;
    const int d0 = blockIdx.x * 64;
    const int dx = threadIdx.x & 63, ry = threadIdx.x >> 6;
    const float* Sb = S  + (size_t)b * EE * DD + d0 + dx;
    float*       Eb = ef + (size_t)b * EE * DD + d0 + dx;

    __shared__ float red[4][64];

    float m = -1e30f;
    for (int e = ry; e < EE; e += 4) m = fmaxf(m, Sb[(size_t)e * DD]);
    red[ry][dx] = m;
    __syncthreads();
    m = fmaxf(fmaxf(red[0][dx], red[1][dx]), fmaxf(red[2][dx], red[3][dx]));
    __syncthreads();

    float s = 0.0f;
    for (int e = ry; e < EE; e += 4) s += __expf(Sb[(size_t)e * DD] - m);
    red[ry][dx] = s;
    __syncthreads();
    s = red[0][dx] + red[1][dx] + red[2][dx] + red[3][dx];
    float inv = 1.0f / s;

    for (int e = ry; e < EE; e += 4) {
        float v = Sb[(size_t)e * DD];
        Eb[(size_t)e * DD] = v * __expf(v - m) * inv;
    }
}

// ---------------------------------------------------------------------------
// LayerNorm (over last dim 256) + residual mix:
//   out = (1+alpha)*prev + (1-alpha)*LN(ef2)
// grid = BB*EE rows, 256 threads (one per column).
// ---------------------------------------------------------------------------
__global__ __launch_bounds__(256) void ln_res(
    const float* __restrict__ ef2, const float* __restrict__ prev,
    const float* __restrict__ gamma, const float* __restrict__ beta,
    const float* __restrict__ alphap, float* __restrict__ out)
{
    const int row = blockIdx.x;
    const int c = threadIdx.x;
    const size_t off = (size_t)row * DD + c;

    float x = ef2[off];
    float s = x, q = x * x;
    #pragma unroll
    for (int o2 = 16; o2 > 0; o2 >>= 1) {
        s += __shfl_down_sync(0xFFFFFFFFu, s, o2);
        q += __shfl_down_sync(0xFFFFFFFFu, q, o2);
    }
    __shared__ float rs[8], rq[8], mv[2];
    int w = c >> 5, l = c & 31;
    if (l == 0) { rs[w] = s; rq[w] = q; }
    __syncthreads();
    if (c == 0) {
        float S2 = 0.0f, Q2 = 0.0f;
        #pragma unroll
        for (int i = 0; i < 8; i++) { S2 += rs[i]; Q2 += rq[i]; }
        float mean = S2 * (1.0f / 256.0f);
        float var  = Q2 * (1.0f / 256.0f) - mean * mean;
        mv[0] = mean;
        mv[1] = rsqrtf(var + 1e-5f);
    }
    __syncthreads();

    float n = (x - mv[0]) * mv[1] * gamma[c] + beta[c];
    float a = *alphap;
    float p = prev[off];
    out[off] = (1.0f + a) * p + (1.0f - a) * n;
}

// ---------------------------------------------------------------------------
// Launch
// ---------------------------------------------------------------------------
extern "C" void kernel_launch(void* const* d_in, const int* in_sizes, int n_in,
                              void* d_out, int out_size)
{
    const float* feat = (const float*)d_in[0];   // [4,2048,256]
    const float* inc  = (const float*)d_in[1];   // [4,2048,1024]
    const float* prev = (const float*)d_in[2];   // [4,1024,256]
    const float* ipw  = (const float*)d_in[3];   // [768,256]
    const float* ipb  = (const float*)d_in[4];   // [768]
    const float* opw  = (const float*)d_in[5];   // [256,256]
    const float* opb  = (const float*)d_in[6];   // [256]
    const float* pw   = (const float*)d_in[7];   // [256,256]
    const float* gam  = (const float*)d_in[8];   // [256]
    const float* bet  = (const float*)d_in[9];   // [256]
    const float* alp  = (const float*)d_in[10];  // [1]
    float* out = (float*)d_out;                  // [4,1024,256]

    float *qkv, *attn, *attnp, *Sb, *ef, *ef2;
    cudaGetSymbolAddress((void**)&qkv,   g_qkv);
    cudaGetSymbolAddress((void**)&attn,  g_attn);
    cudaGetSymbolAddress((void**)&attnp, g_attnp);
    cudaGetSymbolAddress((void**)&Sb,    g_S);
    cudaGetSymbolAddress((void**)&ef,    g_ef);
    cudaGetSymbolAddress((void**)&ef2,   g_ef2);

    // 1. QKV projection: [8192,768] = feat[8192,256] @ in_proj_w^T + b
    sgemm_nt<<<dim3(TD / 64, (BB * MM) / 64), 256>>>(feat, ipw, ipb, qkv,
                                                     BB * MM, TD, DD);
    // 2. attention
    flash_attn<<<dim3(MM / 64, BB * HH), 256>>>(qkv, attn);
    // 3. out projection
    sgemm_nt<<<dim3(DD / 64, (BB * MM) / 64), 256>>>(attn, opw, opb, attnp,
                                                     BB * MM, DD, DD);
    // 4. S = inc^T @ attnp
    sgemm_tn_S<<<dim3(EE / 64, DD / 64, BB), 256>>>(inc, attnp, Sb);
    // 5. ef = S * softmax_e(S)
    col_softmax_mul<<<dim3(DD / 64, BB), 256>>>(Sb, ef);
    // 6. ef2 = ef @ proj_w^T
    sgemm_nt<<<dim3(DD / 64, (BB * EE) / 64), 256>>>(ef, pw, nullptr, ef2,
                                                     BB * EE, DD, DD);
    // 7. LayerNorm + residual mix
    ln_res<<<BB * EE, 256>>>(ef2, prev, gam, bet, alp, out);
}

// round 2
// speedup vs baseline: 2.0615x; 2.0615x over previous
#include <cuda_runtime.h>
#include <cuda_bf16.h>
#include <math.h>
#include <stdint.h>

// Problem constants
#define BB   4
#define MM   2048
#define DD   256
#define EE   1024
#define HH   8
#define DH   32
#define TD   768   // 3*DD

// ---------------------------------------------------------------------------
// Scratch (no cudaMalloc allowed)
// ---------------------------------------------------------------------------
__device__ float g_qkv  [BB * MM * TD];   // 24 MB
__device__ float g_attn [BB * MM * DD];   // 8 MB
__device__ float g_attnp[BB * MM * DD];   // 8 MB
__device__ float g_S    [BB * EE * DD];   // 4 MB
__device__ float g_ef   [BB * EE * DD];   // 4 MB
__device__ float g_ef2  [BB * EE * DD];   // 4 MB

// ---------------------------------------------------------------------------
// tf32 helpers
// ---------------------------------------------------------------------------
__device__ __forceinline__ uint32_t f2t(float x) {
    uint32_t u;
    asm("cvt.rna.tf32.f32 %0, %1;" : "=r"(u) : "f"(x));
    return u;
}

__device__ __forceinline__ void mma_tf32(float* c, const uint32_t* a,
                                         uint32_t b0, uint32_t b1) {
    asm volatile(
        "mma.sync.aligned.m16n8k8.row.col.f32.tf32.tf32.f32 "
        "{%0,%1,%2,%3}, {%4,%5,%6,%7}, {%8,%9}, {%0,%1,%2,%3};\n"
        : "+f"(c[0]), "+f"(c[1]), "+f"(c[2]), "+f"(c[3])
        : "r"(a[0]), "r"(a[1]), "r"(a[2]), "r"(a[3]), "r"(b0), "r"(b1));
}

// ---------------------------------------------------------------------------
// NT GEMM (tf32): C[M,N] = A[M,K] @ W[N,K]^T + bias
// Block 128x64, BK=32, 256 threads (8 warps, 4x2), warp tile 32x32.
// ---------------------------------------------------------------------------
__global__ __launch_bounds__(256) void mm_nt(
    const float* __restrict__ A, const float* __restrict__ W,
    const float* __restrict__ bias, float* __restrict__ C,
    int M, int N, int K)
{
    __shared__ uint32_t As[128][36];
    __shared__ uint32_t Bs[64][36];
    const int tid = threadIdx.x;
    const int lane = tid & 31, wid = tid >> 5;
    const int wm = (wid >> 1) * 32, wn = (wid & 1) * 32;
    const int m0 = blockIdx.y * 128, n0 = blockIdx.x * 64;

    float acc[2][4][4] = {};

    const int ar = tid >> 1, ac = (tid & 1) * 16;   // A stage: 4 float4
    const int br = tid >> 2, bc = (tid & 3) * 8;    // B stage: 2 float4

    for (int k0 = 0; k0 < K; k0 += 32) {
        #pragma unroll
        for (int i = 0; i < 4; i++) {
            float4 v = *(const float4*)&A[(size_t)(m0 + ar) * K + k0 + ac + i * 4];
            As[ar][ac + i * 4 + 0] = f2t(v.x);
            As[ar][ac + i * 4 + 1] = f2t(v.y);
            As[ar][ac + i * 4 + 2] = f2t(v.z);
            As[ar][ac + i * 4 + 3] = f2t(v.w);
        }
        #pragma unroll
        for (int i = 0; i < 2; i++) {
            float4 v = *(const float4*)&W[(size_t)(n0 + br) * K + k0 + bc + i * 4];
            Bs[br][bc + i * 4 + 0] = f2t(v.x);
            Bs[br][bc + i * 4 + 1] = f2t(v.y);
            Bs[br][bc + i * 4 + 2] = f2t(v.z);
            Bs[br][bc + i * 4 + 3] = f2t(v.w);
        }
        __syncthreads();

        #pragma unroll
        for (int kk = 0; kk < 4; kk++) {
            uint32_t a[2][4], b[4][2];
            #pragma unroll
            for (int mi = 0; mi < 2; mi++) {
                int r = wm + mi * 16 + (lane >> 2), c = kk * 8 + (lane & 3);
                a[mi][0] = As[r][c];     a[mi][1] = As[r + 8][c];
                a[mi][2] = As[r][c + 4]; a[mi][3] = As[r + 8][c + 4];
            }
            #pragma unroll
            for (int ni = 0; ni < 4; ni++) {
                int r = wn + ni * 8 + (lane >> 2), c = kk * 8 + (lane & 3);
                b[ni][0] = Bs[r][c]; b[ni][1] = Bs[r][c + 4];
            }
            #pragma unroll
            for (int mi = 0; mi < 2; mi++)
                #pragma unroll
                for (int ni = 0; ni < 4; ni++)
                    mma_tf32(acc[mi][ni], a[mi], b[ni][0], b[ni][1]);
        }
        __syncthreads();
    }

    #pragma unroll
    for (int mi = 0; mi < 2; mi++) {
        #pragma unroll
        for (int ni = 0; ni < 4; ni++) {
            int r = m0 + wm + mi * 16 + (lane >> 2);
            int c = n0 + wn + ni * 8 + 2 * (lane & 3);
            float b0 = bias ? bias[c] : 0.0f;
            float b1 = bias ? bias[c + 1] : 0.0f;
            C[(size_t)r * N + c]           = acc[mi][ni][0] + b0;
            C[(size_t)r * N + c + 1]       = acc[mi][ni][1] + b1;
            C[(size_t)(r + 8) * N + c]     = acc[mi][ni][2] + b0;
            C[(size_t)(r + 8) * N + c + 1] = acc[mi][ni][3] + b1;
        }
    }
}

// ---------------------------------------------------------------------------
// TN GEMM (tf32): S[b,e,d] = sum_m inc[b,m,e] * attn[b,m,d]
// Block 64(e) x 64(d), BK=32(m), 128 threads (4 warps, 2x2), warp tile 32x32.
// Smem staged [k][x] so fragment reads handle the transpose.
// ---------------------------------------------------------------------------
__global__ __launch_bounds__(128) void mm_tn_S(
    const float* __restrict__ inc, const float* __restrict__ attn,
    float* __restrict__ S)
{
    __shared__ uint32_t As[32][72];   // [m-k][e]
    __shared__ uint32_t Bs[32][72];   // [m-k][d]
    const int bz = blockIdx.z;
    const int e0 = blockIdx.x * 64, d0 = blockIdx.y * 64;
    const float* Ab = inc  + (size_t)bz * MM * EE;
    const float* Bb = attn + (size_t)bz * MM * DD;

    const int tid = threadIdx.x;
    const int lane = tid & 31, wid = tid >> 5;
    const int wm = (wid >> 1) * 32, wn = (wid & 1) * 32;

    float acc[2][4][4] = {};

    const int kr = tid >> 2, cb = (tid & 3) * 16;

    for (int k0 = 0; k0 < MM; k0 += 32) {
        #pragma unroll
        for (int i = 0; i < 4; i++) {
            float4 v = *(const float4*)&Ab[(size_t)(k0 + kr) * EE + e0 + cb + i * 4];
            As[kr][cb + i * 4 + 0] = f2t(v.x);
            As[kr][cb + i * 4 + 1] = f2t(v.y);
            As[kr][cb + i * 4 + 2] = f2t(v.z);
            As[kr][cb + i * 4 + 3] = f2t(v.w);
            float4 w = *(const float4*)&Bb[(size_t)(k0 + kr) * DD + d0 + cb + i * 4];
            Bs[kr][cb + i * 4 + 0] = f2t(w.x);
            Bs[kr][cb + i * 4 + 1] = f2t(w.y);
            Bs[kr][cb + i * 4 + 2] = f2t(w.z);
            Bs[kr][cb + i * 4 + 3] = f2t(w.w);
        }
        __syncthreads();

        #pragma unroll
        for (int kk = 0; kk < 4; kk++) {
            uint32_t a[2][4], b[4][2];
            #pragma unroll
            for (int mi = 0; mi < 2; mi++) {
                int kc = kk * 8 + (lane & 3);
                int e  = wm + mi * 16 + (lane >> 2);
                a[mi][0] = As[kc][e];         a[mi][1] = As[kc][e + 8];
                a[mi][2] = As[kc + 4][e];     a[mi][3] = As[kc + 4][e + 8];
            }
            #pragma unroll
            for (int ni = 0; ni < 4; ni++) {
                int kc = kk * 8 + (lane & 3);
                int n  = wn + ni * 8 + (lane >> 2);
                b[ni][0] = Bs[kc][n]; b[ni][1] = Bs[kc + 4][n];
            }
            #pragma unroll
            for (int mi = 0; mi < 2; mi++)
                #pragma unroll
                for (int ni = 0; ni < 4; ni++)
                    mma_tf32(acc[mi][ni], a[mi], b[ni][0], b[ni][1]);
        }
        __syncthreads();
    }

    float* Sb = S + (size_t)bz * EE * DD;
    #pragma unroll
    for (int mi = 0; mi < 2; mi++) {
        #pragma unroll
        for (int ni = 0; ni < 4; ni++) {
            int e = e0 + wm + mi * 16 + (lane >> 2);
            int d = d0 + wn + ni * 8 + 2 * (lane & 3);
            Sb[(size_t)e * DD + d]           = acc[mi][ni][0];
            Sb[(size_t)e * DD + d + 1]       = acc[mi][ni][1];
            Sb[(size_t)(e + 8) * DD + d]     = acc[mi][ni][2];
            Sb[(size_t)(e + 8) * DD + d + 1] = acc[mi][ni][3];
        }
    }
}

// ---------------------------------------------------------------------------
// Flash attention, tf32 mma. One block = 64 query rows of one (b,h).
// 128 threads (4 warps, each owns 16 query rows). BN=64 key tiles.
// ---------------------------------------------------------------------------
__global__ __launch_bounds__(128) void flash_tf32(
    const float* __restrict__ qkv, float* __restrict__ o)
{
    __shared__ uint32_t Ks[64][36];   // [key][dh]
    __shared__ uint32_t Vs[64][40];   // [key][dh]
    __shared__ uint32_t Ps[64][68];   // [q-row][key]; also Q staging scratch

    const int bh = blockIdx.y;
    const int b = bh >> 3, h = bh & 7;
    const int m0 = blockIdx.x * 64;
    const int tid = threadIdx.x;
    const int lane = tid & 31;
    const int w16 = (tid >> 5) * 16;

    const float scale = 0.1767766952966369f;   // 1/sqrt(32)
    const size_t base = (size_t)(b * MM) * TD + h * DH;

    // ---- stage Q (scaled, tf32) into Ps scratch, pull into A-fragments ----
    {
        const int r = tid >> 1, cb = (tid & 1) * 16;
        const float* qp = &qkv[base + (size_t)(m0 + r) * TD + cb];
        #pragma unroll
        for (int i = 0; i < 4; i++) {
            float4 v = *(const float4*)&qp[i * 4];
            Ps[r][cb + i * 4 + 0] = f2t(v.x * scale);
            Ps[r][cb + i * 4 + 1] = f2t(v.y * scale);
            Ps[r][cb + i * 4 + 2] = f2t(v.z * scale);
            Ps[r][cb + i * 4 + 3] = f2t(v.w * scale);
        }
    }
    __syncthreads();
    uint32_t qa[4][4];
    #pragma unroll
    for (int kk = 0; kk < 4; kk++) {
        int r = w16 + (lane >> 2), c = kk * 8 + (lane & 3);
        qa[kk][0] = Ps[r][c];     qa[kk][1] = Ps[r + 8][c];
        qa[kk][2] = Ps[r][c + 4]; qa[kk][3] = Ps[r + 8][c + 4];
    }
    __syncthreads();

    float O[4][4] = {};
    float mr0 = -1e30f, mr1 = -1e30f, l0 = 0.0f, l1 = 0.0f;

    for (int kt = 0; kt < MM; kt += 64) {
        // ---- stage K, V tiles (tf32) ----
        {
            const int r = tid >> 1, cb = (tid & 1) * 16;
            const float* kp = &qkv[base + (size_t)(kt + r) * TD + 256 + cb];
            #pragma unroll
            for (int i = 0; i < 4; i++) {
                float4 kv = *(const float4*)&kp[i * 4];
                float4 vv = *(const float4*)&kp[256 + i * 4];
                Ks[r][cb + i * 4 + 0] = f2t(kv.x);
                Ks[r][cb + i * 4 + 1] = f2t(kv.y);
                Ks[r][cb + i * 4 + 2] = f2t(kv.z);
                Ks[r][cb + i * 4 + 3] = f2t(kv.w);
                Vs[r][cb + i * 4 + 0] = f2t(vv.x);
                Vs[r][cb + i * 4 + 1] = f2t(vv.y);
                Vs[r][cb + i * 4 + 2] = f2t(vv.z);
                Vs[r][cb + i * 4 + 3] = f2t(vv.w);
            }
        }
        __syncthreads();

        // ---- S = Q @ K^T : 8 n-frags x 4 k-chunks ----
        float sa[8][4] = {};
        #pragma unroll
        for (int j = 0; j < 8; j++) {
            #pragma unroll
            for (int kk = 0; kk < 4; kk++) {
                uint32_t b0 = Ks[j * 8 + (lane >> 2)][kk * 8 + (lane & 3)];
                uint32_t b1 = Ks[j * 8 + (lane >> 2)][kk * 8 + (lane & 3) + 4];
                mma_tf32(sa[j], qa[kk], b0, b1);
            }
        }

        // ---- online softmax (rows r0 = w16+lane>>2, r1 = r0+8) ----
        float mx0 = -1e30f, mx1 = -1e30f;
        #pragma unroll
        for (int j = 0; j < 8; j++) {
            mx0 = fmaxf(mx0, fmaxf(sa[j][0], sa[j][1]));
            mx1 = fmaxf(mx1, fmaxf(sa[j][2], sa[j][3]));
        }
        mx0 = fmaxf(mx0, __shfl_xor_sync(0xFFFFFFFFu, mx0, 1));
        mx0 = fmaxf(mx0, __shfl_xor_sync(0xFFFFFFFFu, mx0, 2));
        mx1 = fmaxf(mx1, __shfl_xor_sync(0xFFFFFFFFu, mx1, 1));
        mx1 = fmaxf(mx1, __shfl_xor_sync(0xFFFFFFFFu, mx1, 2));

        float mn0 = fmaxf(mr0, mx0), mn1 = fmaxf(mr1, mx1);
        float al0 = __expf(mr0 - mn0), al1 = __expf(mr1 - mn1);
        mr0 = mn0; mr1 = mn1;

        float s0 = 0.0f, s1 = 0.0f;
        const int pr = w16 + (lane >> 2);
        #pragma unroll
        for (int j = 0; j < 8; j++) {
            float p00 = __expf(sa[j][0] - mn0);
            float p01 = __expf(sa[j][1] - mn0);
            float p10 = __expf(sa[j][2] - mn1);
            float p11 = __expf(sa[j][3] - mn1);
            s0 += p00 + p01; s1 += p10 + p11;
            int pc = j * 8 + 2 * (lane & 3);
            Ps[pr][pc]         = f2t(p00);
            Ps[pr][pc + 1]     = f2t(p01);
            Ps[pr + 8][pc]     = f2t(p10);
            Ps[pr + 8][pc + 1] = f2t(p11);
        }
        s0 += __shfl_xor_sync(0xFFFFFFFFu, s0, 1);
        s0 += __shfl_xor_sync(0xFFFFFFFFu, s0, 2);
        s1 += __shfl_xor_sync(0xFFFFFFFFu, s1, 1);
        s1 += __shfl_xor_sync(0xFFFFFFFFu, s1, 2);
        l0 = l0 * al0 + s0;
        l1 = l1 * al1 + s1;
        #pragma unroll
        for (int ni = 0; ni < 4; ni++) {
            O[ni][0] *= al0; O[ni][1] *= al0;
            O[ni][2] *= al1; O[ni][3] *= al1;
        }
        __syncwarp();

        // ---- O += P @ V : k-dim 64 (8 chunks), n = 32 (4 frags) ----
        #pragma unroll
        for (int kc = 0; kc < 8; kc++) {
            uint32_t pa[4];
            int c = kc * 8 + (lane & 3);
            pa[0] = Ps[pr][c];     pa[1] = Ps[pr + 8][c];
            pa[2] = Ps[pr][c + 4]; pa[3] = Ps[pr + 8][c + 4];
            #pragma unroll
            for (int ni = 0; ni < 4; ni++) {
                uint32_t b0 = Vs[kc * 8 + (lane & 3)][ni * 8 + (lane >> 2)];
                uint32_t b1 = Vs[kc * 8 + (lane & 3) + 4][ni * 8 + (lane >> 2)];
                mma_tf32(O[ni], pa, b0, b1);
            }
        }
        __syncthreads();
    }

    const float inv0 = 1.0f / l0, inv1 = 1.0f / l1;
    #pragma unroll
    for (int ni = 0; ni < 4; ni++) {
        int row = m0 + w16 + (lane >> 2);
        int col = h * DH + ni * 8 + 2 * (lane & 3);
        size_t off = ((size_t)(b * MM) + row) * DD + col;
        o[off]              = O[ni][0] * inv0;
        o[off + 1]          = O[ni][1] * inv0;
        o[off + 8 * DD]     = O[ni][2] * inv1;
        o[off + 8 * DD + 1] = O[ni][3] * inv1;
    }
}

// ---------------------------------------------------------------------------
// Column softmax over e + multiply:  ef = S * softmax_e(S)
// ---------------------------------------------------------------------------
__global__ __launch_bounds__(256) void col_softmax_mul(
    const float* __restrict__ S, float* __restrict__ ef)
{
    const int b  = blockIdx.y;
    const int d0 = blockIdx.x * 64;
    const int dx = threadIdx.x & 63, ry = threadIdx.x >> 6;
    const float* Sb = S  + (size_t)b * EE * DD + d0 + dx;
    float*       Eb = ef + (size_t)b * EE * DD + d0 + dx;

    __shared__ float red[4][64];

    float m = -1e30f;
    for (int e = ry; e < EE; e += 4) m = fmaxf(m, Sb[(size_t)e * DD]);
    red[ry][dx] = m;
    __syncthreads();
    m = fmaxf(fmaxf(red[0][dx], red[1][dx]), fmaxf(red[2][dx], red[3][dx]));
    __syncthreads();

    float s = 0.0f;
    for (int e = ry; e < EE; e += 4) s += __expf(Sb[(size_t)e * DD] - m);
    red[ry][dx] = s;
    __syncthreads();
    s = red[0][dx] + red[1][dx] + red[2][dx] + red[3][dx];
    float inv = 1.0f / s;

    for (int e = ry; e < EE; e += 4) {
        float v = Sb[(size_t)e * DD];
        Eb[(size_t)e * DD] = v * __expf(v - m) * inv;
    }
}

// ---------------------------------------------------------------------------
// LayerNorm (dim 256) + residual mix:  out = (1+alpha)*prev + (1-alpha)*LN(x)
// ---------------------------------------------------------------------------
__global__ __launch_bounds__(256) void ln_res(
    const float* __restrict__ ef2, const float* __restrict__ prev,
    const float* __restrict__ gamma, const float* __restrict__ beta,
    const float* __restrict__ alphap, float* __restrict__ out)
{
    const int row = blockIdx.x;
    const int c = threadIdx.x;
    const size_t off = (size_t)row * DD + c;

    float x = ef2[off];
    float s = x, q = x * x;
    #pragma unroll
    for (int o2 = 16; o2 > 0; o2 >>= 1) {
        s += __shfl_down_sync(0xFFFFFFFFu, s, o2);
        q += __shfl_down_sync(0xFFFFFFFFu, q, o2);
    }
    __shared__ float rs[8], rq[8], mv[2];
    int w = c >> 5, l = c & 31;
    if (l == 0) { rs[w] = s; rq[w] = q; }
    __syncthreads();
    if (c == 0) {
        float S2 = 0.0f, Q2 = 0.0f;
        #pragma unroll
        for (int i = 0; i < 8; i++) { S2 += rs[i]; Q2 += rq[i]; }
        float mean = S2 * (1.0f / 256.0f);
        float var  = Q2 * (1.0f / 256.0f) - mean * mean;
        mv[0] = mean;
        mv[1] = rsqrtf(var + 1e-5f);
    }
    __syncthreads();

    float n = (x - mv[0]) * mv[1] * gamma[c] + beta[c];
    float a = *alphap;
    float p = prev[off];
    out[off] = (1.0f + a) * p + (1.0f - a) * n;
}

// ---------------------------------------------------------------------------
// Launch
// ---------------------------------------------------------------------------
extern "C" void kernel_launch(void* const* d_in, const int* in_sizes, int n_in,
                              void* d_out, int out_size)
{
    const float* feat = (const float*)d_in[0];
    const float* inc  = (const float*)d_in[1];
    const float* prev = (const float*)d_in[2];
    const float* ipw  = (const float*)d_in[3];
    const float* ipb  = (const float*)d_in[4];
    const float* opw  = (const float*)d_in[5];
    const float* opb  = (const float*)d_in[6];
    const float* pw   = (const float*)d_in[7];
    const float* gam  = (const float*)d_in[8];
    const float* bet  = (const float*)d_in[9];
    const float* alp  = (const float*)d_in[10];
    float* out = (float*)d_out;

    float *qkv, *attn, *attnp, *Sb, *ef, *ef2;
    cudaGetSymbolAddress((void**)&qkv,   g_qkv);
    cudaGetSymbolAddress((void**)&attn,  g_attn);
    cudaGetSymbolAddress((void**)&attnp, g_attnp);
    cudaGetSymbolAddress((void**)&Sb,    g_S);
    cudaGetSymbolAddress((void**)&ef,    g_ef);
    cudaGetSymbolAddress((void**)&ef2,   g_ef2);

    // 1. QKV projection: [8192,768]
    mm_nt<<<dim3(TD / 64, (BB * MM) / 128), 256>>>(feat, ipw, ipb, qkv,
                                                   BB * MM, TD, DD);
    // 2. flash attention
    flash_tf32<<<dim3(MM / 64, BB * HH), 128>>>(qkv, attn);
    // 3. out projection: [8192,256]
    mm_nt<<<dim3(DD / 64, (BB * MM) / 128), 256>>>(attn, opw, opb, attnp,
                                                   BB * MM, DD, DD);
    // 4. S = inc^T @ attnp
    mm_tn_S<<<dim3(EE / 64, DD / 64, BB), 128>>>(inc, attnp, Sb);
    // 5. ef = S * softmax_e(S)
    col_softmax_mul<<<dim3(DD / 64, BB), 256>>>(Sb, ef);
    // 6. ef2 = ef @ proj_w^T: [4096,256]
    mm_nt<<<dim3(DD / 64, (BB * EE) / 128), 256>>>(ef, pw, nullptr, ef2,
                                                   BB * EE, DD, DD);
    // 7. LayerNorm + residual mix
    ln_res<<<BB * EE, 256>>>(ef2, prev, gam, bet, alp, out);
}

// round 4
// speedup vs baseline: 2.2896x; 1.1107x over previous
#include <cuda_runtime.h>
#include <cuda_bf16.h>
#include <math.h>
#include <stdint.h>

// Problem constants
#define BB   4
#define MM   2048
#define DD   256
#define EE   1024
#define HH   8
#define DH   32
#define TD   768   // 3*DD
#define NSPLIT 4
#define KS   (MM / NSPLIT)   // 512

// ---------------------------------------------------------------------------
// Scratch (no cudaMalloc allowed)
// ---------------------------------------------------------------------------
__device__ float g_qkv  [BB * MM * TD];          // 24 MB
__device__ float g_attn [BB * MM * DD];          // 8 MB
__device__ float g_attnp[BB * MM * DD];          // 8 MB
__device__ float g_Sp   [NSPLIT * BB * EE * DD]; // 16 MB (split-K partials)
__device__ float g_S    [BB * EE * DD];          // 4 MB
__device__ float g_ef   [BB * EE * DD];          // 4 MB
__device__ float g_ef2  [BB * EE * DD];          // 4 MB

// ---------------------------------------------------------------------------
// tf32 helpers
// ---------------------------------------------------------------------------
__device__ __forceinline__ uint32_t f2t(float x) {
    uint32_t u;
    asm("cvt.rna.tf32.f32 %0, %1;" : "=r"(u) : "f"(x));
    return u;
}

__device__ __forceinline__ void mma_tf32(float* c, const uint32_t* a,
                                         uint32_t b0, uint32_t b1) {
    asm volatile(
        "mma.sync.aligned.m16n8k8.row.col.f32.tf32.tf32.f32 "
        "{%0,%1,%2,%3}, {%4,%5,%6,%7}, {%8,%9}, {%0,%1,%2,%3};\n"
        : "+f"(c[0]), "+f"(c[1]), "+f"(c[2]), "+f"(c[3])
        : "r"(a[0]), "r"(a[1]), "r"(a[2]), "r"(a[3]), "r"(b0), "r"(b1));
}

// ---------------------------------------------------------------------------
// NT GEMM 128x64 tile (tf32, double-buffered): C = A[M,K] @ W[N,K]^T + bias
// 256 threads, 8 warps (4x2), warp tile 32x32, BK=32.
// ---------------------------------------------------------------------------
__global__ __launch_bounds__(256) void mm_nt128(
    const float* __restrict__ A, const float* __restrict__ W,
    const float* __restrict__ bias, float* __restrict__ C,
    int M, int N, int K)
{
    __shared__ uint32_t As[2][128][36];
    __shared__ uint32_t Bs[2][64][36];
    const int tid = threadIdx.x;
    const int lane = tid & 31, wid = tid >> 5;
    const int wm = (wid >> 1) * 32, wn = (wid & 1) * 32;
    const int m0 = blockIdx.y * 128, n0 = blockIdx.x * 64;

    const int ar = tid >> 1, ac = (tid & 1) * 16;
    const int br = tid >> 2, bc = (tid & 3) * 8;

    float acc[2][4][4] = {};
    float4 pa[4], pb[2];

    const float* Ap = &A[(size_t)(m0 + ar) * K + ac];
    const float* Wp = &W[(size_t)(n0 + br) * K + bc];

    #pragma unroll
    for (int i = 0; i < 4; i++) pa[i] = *(const float4*)&Ap[i * 4];
    #pragma unroll
    for (int i = 0; i < 2; i++) pb[i] = *(const float4*)&Wp[i * 4];

    const int nk = K >> 5;
    for (int t = 0; t < nk; t++) {
        const int s = t & 1;
        #pragma unroll
        for (int i = 0; i < 4; i++) {
            As[s][ar][ac + i * 4 + 0] = f2t(pa[i].x);
            As[s][ar][ac + i * 4 + 1] = f2t(pa[i].y);
            As[s][ar][ac + i * 4 + 2] = f2t(pa[i].z);
            As[s][ar][ac + i * 4 + 3] = f2t(pa[i].w);
        }
        #pragma unroll
        for (int i = 0; i < 2; i++) {
            Bs[s][br][bc + i * 4 + 0] = f2t(pb[i].x);
            Bs[s][br][bc + i * 4 + 1] = f2t(pb[i].y);
            Bs[s][br][bc + i * 4 + 2] = f2t(pb[i].z);
            Bs[s][br][bc + i * 4 + 3] = f2t(pb[i].w);
        }
        if (t + 1 < nk) {
            const float* Ap2 = Ap + (t + 1) * 32;
            const float* Wp2 = Wp + (t + 1) * 32;
            #pragma unroll
            for (int i = 0; i < 4; i++) pa[i] = *(const float4*)&Ap2[i * 4];
            #pragma unroll
            for (int i = 0; i < 2; i++) pb[i] = *(const float4*)&Wp2[i * 4];
        }
        __syncthreads();

        #pragma unroll
        for (int kk = 0; kk < 4; kk++) {
            uint32_t a[2][4], b[4][2];
            #pragma unroll
            for (int mi = 0; mi < 2; mi++) {
                int r = wm + mi * 16 + (lane >> 2), c = kk * 8 + (lane & 3);
                a[mi][0] = As[s][r][c];     a[mi][1] = As[s][r + 8][c];
                a[mi][2] = As[s][r][c + 4]; a[mi][3] = As[s][r + 8][c + 4];
            }
            #pragma unroll
            for (int ni = 0; ni < 4; ni++) {
                int r = wn + ni * 8 + (lane >> 2), c = kk * 8 + (lane & 3);
                b[ni][0] = Bs[s][r][c]; b[ni][1] = Bs[s][r][c + 4];
            }
            #pragma unroll
            for (int mi = 0; mi < 2; mi++)
                #pragma unroll
                for (int ni = 0; ni < 4; ni++)
                    mma_tf32(acc[mi][ni], a[mi], b[ni][0], b[ni][1]);
        }
    }

    #pragma unroll
    for (int mi = 0; mi < 2; mi++) {
        #pragma unroll
        for (int ni = 0; ni < 4; ni++) {
            int r = m0 + wm + mi * 16 + (lane >> 2);
            int c = n0 + wn + ni * 8 + 2 * (lane & 3);
            float b0 = bias ? bias[c] : 0.0f;
            float b1 = bias ? bias[c + 1] : 0.0f;
            C[(size_t)r * N + c]           = acc[mi][ni][0] + b0;
            C[(size_t)r * N + c + 1]       = acc[mi][ni][1] + b1;
            C[(size_t)(r + 8) * N + c]     = acc[mi][ni][2] + b0;
            C[(size_t)(r + 8) * N + c + 1] = acc[mi][ni][3] + b1;
        }
    }
}

// ---------------------------------------------------------------------------
// NT GEMM 64x64 tile (tf32, double-buffered): for small-M GEMMs (more CTAs).
// 128 threads, 4 warps (2x2), warp tile 32x32, BK=32.
// ---------------------------------------------------------------------------
__global__ __launch_bounds__(128) void mm_nt64(
    const float* __restrict__ A, const float* __restrict__ W,
    const float* __restrict__ bias, float* __restrict__ C,
    int M, int N, int K)
{
    __shared__ uint32_t As[2][64][36];
    __shared__ uint32_t Bs[2][64][36];
    const int tid = threadIdx.x;
    const int lane = tid & 31, wid = tid >> 5;
    const int wm = (wid >> 1) * 32, wn = (wid & 1) * 32;
    const int m0 = blockIdx.y * 64, n0 = blockIdx.x * 64;

    const int sr = tid >> 1, sc = (tid & 1) * 16;

    float acc[2][4][4] = {};
    float4 pa[4], pb[4];

    const float* Ap = &A[(size_t)(m0 + sr) * K + sc];
    const float* Wp = &W[(size_t)(n0 + sr) * K + sc];

    #pragma unroll
    for (int i = 0; i < 4; i++) {
        pa[i] = *(const float4*)&Ap[i * 4];
        pb[i] = *(const float4*)&Wp[i * 4];
    }

    const int nk = K >> 5;
    for (int t = 0; t < nk; t++) {
        const int s = t & 1;
        #pragma unroll
        for (int i = 0; i < 4; i++) {
            As[s][sr][sc + i * 4 + 0] = f2t(pa[i].x);
            As[s][sr][sc + i * 4 + 1] = f2t(pa[i].y);
            As[s][sr][sc + i * 4 + 2] = f2t(pa[i].z);
            As[s][sr][sc + i * 4 + 3] = f2t(pa[i].w);
            Bs[s][sr][sc + i * 4 + 0] = f2t(pb[i].x);
            Bs[s][sr][sc + i * 4 + 1] = f2t(pb[i].y);
            Bs[s][sr][sc + i * 4 + 2] = f2t(pb[i].z);
            Bs[s][sr][sc + i * 4 + 3] = f2t(pb[i].w);
        }
        if (t + 1 < nk) {
            const float* Ap2 = Ap + (t + 1) * 32;
            const float* Wp2 = Wp + (t + 1) * 32;
            #pragma unroll
            for (int i = 0; i < 4; i++) {
                pa[i] = *(const float4*)&Ap2[i * 4];
                pb[i] = *(const float4*)&Wp2[i * 4];
            }
        }
        __syncthreads();

        #pragma unroll
        for (int kk = 0; kk < 4; kk++) {
            uint32_t a[2][4], b[4][2];
            #pragma unroll
            for (int mi = 0; mi < 2; mi++) {
                int r = wm + mi * 16 + (lane >> 2), c = kk * 8 + (lane & 3);
                a[mi][0] = As[s][r][c];     a[mi][1] = As[s][r + 8][c];
                a[mi][2] = As[s][r][c + 4]; a[mi][3] = As[s][r + 8][c + 4];
            }
            #pragma unroll
            for (int ni = 0; ni < 4; ni++) {
                int r = wn + ni * 8 + (lane >> 2), c = kk * 8 + (lane & 3);
                b[ni][0] = Bs[s][r][c]; b[ni][1] = Bs[s][r][c + 4];
            }
            #pragma unroll
            for (int mi = 0; mi < 2; mi++)
                #pragma unroll
                for (int ni = 0; ni < 4; ni++)
                    mma_tf32(acc[mi][ni], a[mi], b[ni][0], b[ni][1]);
        }
    }

    #pragma unroll
    for (int mi = 0; mi < 2; mi++) {
        #pragma unroll
        for (int ni = 0; ni < 4; ni++) {
            int r = m0 + wm + mi * 16 + (lane >> 2);
            int c = n0 + wn + ni * 8 + 2 * (lane & 3);
            float b0 = bias ? bias[c] : 0.0f;
            float b1 = bias ? bias[c + 1] : 0.0f;
            C[(size_t)r * N + c]           = acc[mi][ni][0] + b0;
            C[(size_t)r * N + c + 1]       = acc[mi][ni][1] + b1;
            C[(size_t)(r + 8) * N + c]     = acc[mi][ni][2] + b0;
            C[(size_t)(r + 8) * N + c + 1] = acc[mi][ni][3] + b1;
        }
    }
}

// ---------------------------------------------------------------------------
// TN GEMM split-K (tf32, double-buffered):
//   Sp[sp,b,e,d] = sum_{m in split sp} inc[b,m,e] * attn[b,m,d]
// Block 64(e) x 64(d), BK=32, 128 threads (2x2 warps), blockIdx.z = b*4+split.
// ---------------------------------------------------------------------------
__global__ __launch_bounds__(128) void mm_tn_S(
    const float* __restrict__ inc, const float* __restrict__ attn,
    float* __restrict__ Sp)
{
    __shared__ uint32_t As[2][32][72];   // [m-k][e]
    __shared__ uint32_t Bs[2][32][72];   // [m-k][d]
    const int zz = blockIdx.z;
    const int bz = zz >> 2, sp = zz & 3;
    const int e0 = blockIdx.x * 64, d0 = blockIdx.y * 64;
    const float* Ab = inc  + (size_t)bz * MM * EE + (size_t)(sp * KS) * EE;
    const float* Bb = attn + (size_t)bz * MM * DD + (size_t)(sp * KS) * DD;

    const int tid = threadIdx.x;
    const int lane = tid & 31, wid = tid >> 5;
    const int wm = (wid >> 1) * 32, wn = (wid & 1) * 32;

    const int kr = tid >> 2, cb = (tid & 3) * 16;

    float acc[2][4][4] = {};
    float4 pa[4], pb[4];

    #pragma unroll
    for (int i = 0; i < 4; i++) {
        pa[i] = *(const float4*)&Ab[(size_t)kr * EE + e0 + cb + i * 4];
        pb[i] = *(const float4*)&Bb[(size_t)kr * DD + d0 + cb + i * 4];
    }

    const int nk = KS >> 5;   // 16
    for (int t = 0; t < nk; t++) {
        const int s = t & 1;
        #pragma unroll
        for (int i = 0; i < 4; i++) {
            As[s][kr][cb + i * 4 + 0] = f2t(pa[i].x);
            As[s][kr][cb + i * 4 + 1] = f2t(pa[i].y);
            As[s][kr][cb + i * 4 + 2] = f2t(pa[i].z);
            As[s][kr][cb + i * 4 + 3] = f2t(pa[i].w);
            Bs[s][kr][cb + i * 4 + 0] = f2t(pb[i].x);
            Bs[s][kr][cb + i * 4 + 1] = f2t(pb[i].y);
            Bs[s][kr][cb + i * 4 + 2] = f2t(pb[i].z);
            Bs[s][kr][cb + i * 4 + 3] = f2t(pb[i].w);
        }
        if (t + 1 < nk) {
            int kn = (t + 1) * 32 + kr;
            #pragma unroll
            for (int i = 0; i < 4; i++) {
                pa[i] = *(const float4*)&Ab[(size_t)kn * EE + e0 + cb + i * 4];
                pb[i] = *(const float4*)&Bb[(size_t)kn * DD + d0 + cb + i * 4];
            }
        }
        __syncthreads();

        #pragma unroll
        for (int kk = 0; kk < 4; kk++) {
            uint32_t a[2][4], b[4][2];
            #pragma unroll
            for (int mi = 0; mi < 2; mi++) {
                int kc = kk * 8 + (lane & 3);
                int e  = wm + mi * 16 + (lane >> 2);
                a[mi][0] = As[s][kc][e];     a[mi][1] = As[s][kc][e + 8];
                a[mi][2] = As[s][kc + 4][e]; a[mi][3] = As[s][kc + 4][e + 8];
            }
            #pragma unroll
            for (int ni = 0; ni < 4; ni++) {
                int kc = kk * 8 + (lane & 3);
                int n  = wn + ni * 8 + (lane >> 2);
                b[ni][0] = Bs[s][kc][n]; b[ni][1] = Bs[s][kc + 4][n];
            }
            #pragma unroll
            for (int mi = 0; mi < 2; mi++)
                #pragma unroll
                for (int ni = 0; ni < 4; ni++)
                    mma_tf32(acc[mi][ni], a[mi], b[ni][0], b[ni][1]);
        }
    }

    float* Sb = Sp + ((size_t)(sp * BB + bz)) * EE * DD;
    #pragma unroll
    for (int mi = 0; mi < 2; mi++) {
        #pragma unroll
        for (int ni = 0; ni < 4; ni++) {
            int e = e0 + wm + mi * 16 + (lane >> 2);
            int d = d0 + wn + ni * 8 + 2 * (lane & 3);
            Sb[(size_t)e * DD + d]           = acc[mi][ni][0];
            Sb[(size_t)e * DD + d + 1]       = acc[mi][ni][1];
            Sb[(size_t)(e + 8) * DD + d]     = acc[mi][ni][2];
            Sb[(size_t)(e + 8) * DD + d + 1] = acc[mi][ni][3];
        }
    }
}

// Reduce split-K partials: S = sum_sp Sp[sp]
__global__ __launch_bounds__(256) void reduce_S(
    const float4* __restrict__ Sp, float4* __restrict__ S)
{
    const size_t N4 = (size_t)BB * EE * DD / 4;
    size_t i = (size_t)blockIdx.x * 256 + threadIdx.x;
    if (i >= N4) return;
    float4 a = Sp[i], b = Sp[i + N4], c = Sp[i + 2 * N4], d = Sp[i + 3 * N4];
    float4 r;
    r.x = (a.x + b.x) + (c.x + d.x);
    r.y = (a.y + b.y) + (c.y + d.y);
    r.z = (a.z + b.z) + (c.z + d.z);
    r.w = (a.w + b.w) + (c.w + d.w);
    S[i] = r;
}

// ---------------------------------------------------------------------------
// Flash attention, tf32 mma. One block = 128 query rows of one (b,h).
// 256 threads / 8 warps; each warp owns 16 q-rows. Key tile BN=64,
// K/V double-buffered via register prefetch; one block sync per key tile.
// ---------------------------------------------------------------------------
__global__ __launch_bounds__(256) void flash_tf32(
    const float* __restrict__ qkv, float* __restrict__ o)
{
    __shared__ uint32_t Ks[2][64][36];   // [key][dh]
    __shared__ uint32_t Vs[2][64][40];   // [key][dh]
    __shared__ uint32_t Ps[128][68];     // [q-row][key]; also Q staging

    const int bh = blockIdx.y;
    const int b = bh >> 3, h = bh & 7;
    const int m0 = blockIdx.x * 128;
    const int tid = threadIdx.x;
    const int lane = tid & 31;
    const int w16 = (tid >> 5) * 16;

    const float scale = 0.1767766952966369f;   // 1/sqrt(32)
    const size_t base = (size_t)(b * MM) * TD + h * DH;

    // ---- stage Q (scaled, tf32) via Ps scratch, pull A-fragments ----
    {
        const int r = tid >> 1, cb = (tid & 1) * 16;
        const float* qp = &qkv[base + (size_t)(m0 + r) * TD + cb];
        #pragma unroll
        for (int i = 0; i < 4; i++) {
            float4 v = *(const float4*)&qp[i * 4];
            Ps[r][cb + i * 4 + 0] = f2t(v.x * scale);
            Ps[r][cb + i * 4 + 1] = f2t(v.y * scale);
            Ps[r][cb + i * 4 + 2] = f2t(v.z * scale);
            Ps[r][cb + i * 4 + 3] = f2t(v.w * scale);
        }
    }
    __syncthreads();
    uint32_t qa[4][4];
    #pragma unroll
    for (int kk = 0; kk < 4; kk++) {
        int r = w16 + (lane >> 2), c = kk * 8 + (lane & 3);
        qa[kk][0] = Ps[r][c];     qa[kk][1] = Ps[r + 8][c];
        qa[kk][2] = Ps[r][c + 4]; qa[kk][3] = Ps[r + 8][c + 4];
    }
    __syncthreads();

    float O[4][4] = {};
    float mr0 = -1e30f, mr1 = -1e30f, l0 = 0.0f, l1 = 0.0f;

    // K/V staging: rk = key row (0..63), ck = dh col base (8 per thread each)
    const int rk = tid >> 2, ck = (tid & 3) * 8;
    float4 kpr[2], vpr[2];
    {
        const float* kp = &qkv[base + (size_t)rk * TD + 256 + ck];
        kpr[0] = *(const float4*)&kp[0];
        kpr[1] = *(const float4*)&kp[4];
        vpr[0] = *(const float4*)&kp[256];
        vpr[1] = *(const float4*)&kp[260];
    }

    const int ntile = MM / 64;
    for (int t = 0; t < ntile; t++) {
        const int s = t & 1;
        #pragma unroll
        for (int i = 0; i < 2; i++) {
            Ks[s][rk][ck + i * 4 + 0] = f2t(kpr[i].x);
            Ks[s][rk][ck + i * 4 + 1] = f2t(kpr[i].y);
            Ks[s][rk][ck + i * 4 + 2] = f2t(kpr[i].z);
            Ks[s][rk][ck + i * 4 + 3] = f2t(kpr[i].w);
            Vs[s][rk][ck + i * 4 + 0] = f2t(vpr[i].x);
            Vs[s][rk][ck + i * 4 + 1] = f2t(vpr[i].y);
            Vs[s][rk][ck + i * 4 + 2] = f2t(vpr[i].z);
            Vs[s][rk][ck + i * 4 + 3] = f2t(vpr[i].w);
        }
        if (t + 1 < ntile) {
            const float* kp = &qkv[base + (size_t)((t + 1) * 64 + rk) * TD + 256 + ck];
            kpr[0] = *(const float4*)&kp[0];
            kpr[1] = *(const float4*)&kp[4];
            vpr[0] = *(const float4*)&kp[256];
            vpr[1] = *(const float4*)&kp[260];
        }
        __syncthreads();

        // ---- S = Q @ K^T ----
        float sa[8][4] = {};
        #pragma unroll
        for (int j = 0; j < 8; j++) {
            #pragma unroll
            for (int kk = 0; kk < 4; kk++) {
                uint32_t b0 = Ks[s][j * 8 + (lane >> 2)][kk * 8 + (lane & 3)];
                uint32_t b1 = Ks[s][j * 8 + (lane >> 2)][kk * 8 + (lane & 3) + 4];
                mma_tf32(sa[j], qa[kk], b0, b1);
            }
        }

        // ---- online softmax ----
        float mx0 = -1e30f, mx1 = -1e30f;
        #pragma unroll
        for (int j = 0; j < 8; j++) {
            mx0 = fmaxf(mx0, fmaxf(sa[j][0], sa[j][1]));
            mx1 = fmaxf(mx1, fmaxf(sa[j][2], sa[j][3]));
        }
        mx0 = fmaxf(mx0, __shfl_xor_sync(0xFFFFFFFFu, mx0, 1));
        mx0 = fmaxf(mx0, __shfl_xor_sync(0xFFFFFFFFu, mx0, 2));
        mx1 = fmaxf(mx1, __shfl_xor_sync(0xFFFFFFFFu, mx1, 1));
        mx1 = fmaxf(mx1, __shfl_xor_sync(0xFFFFFFFFu, mx1, 2));

        float mn0 = fmaxf(mr0, mx0), mn1 = fmaxf(mr1, mx1);
        float al0 = __expf(mr0 - mn0), al1 = __expf(mr1 - mn1);
        mr0 = mn0; mr1 = mn1;

        float s0 = 0.0f, s1 = 0.0f;
        const int pr = w16 + (lane >> 2);
        #pragma unroll
        for (int j = 0; j < 8; j++) {
            float p00 = __expf(sa[j][0] - mn0);
            float p01 = __expf(sa[j][1] - mn0);
            float p10 = __expf(sa[j][2] - mn1);
            float p11 = __expf(sa[j][3] - mn1);
            s0 += p00 + p01; s1 += p10 + p11;
            int pc = j * 8 + 2 * (lane & 3);
            Ps[pr][pc]         = f2t(p00);
            Ps[pr][pc + 1]     = f2t(p01);
            Ps[pr + 8][pc]     = f2t(p10);
            Ps[pr + 8][pc + 1] = f2t(p11);
        }
        s0 += __shfl_xor_sync(0xFFFFFFFFu, s0, 1);
        s0 += __shfl_xor_sync(0xFFFFFFFFu, s0, 2);
        s1 += __shfl_xor_sync(0xFFFFFFFFu, s1, 1);
        s1 += __shfl_xor_sync(0xFFFFFFFFu, s1, 2);
        l0 = l0 * al0 + s0;
        l1 = l1 * al1 + s1;
        #pragma unroll
        for (int ni = 0; ni < 4; ni++) {
            O[ni][0] *= al0; O[ni][1] *= al0;
            O[ni][2] *= al1; O[ni][3] *= al1;
        }
        __syncwarp();

        // ---- O += P @ V (P warp-private in Ps) ----
        #pragma unroll
        for (int kc = 0; kc < 8; kc++) {
            uint32_t pa[4];
            int c = kc * 8 + (lane & 3);
            pa[0] = Ps[pr][c];     pa[1] = Ps[pr + 8][c];
            pa[2] = Ps[pr][c + 4]; pa[3] = Ps[pr + 8][c + 4];
            #pragma unroll
            for (int ni = 0; ni < 4; ni++) {
                uint32_t b0 = Vs[s][kc * 8 + (lane & 3)][ni * 8 + (lane >> 2)];
                uint32_t b1 = Vs[s][kc * 8 + (lane & 3) + 4][ni * 8 + (lane >> 2)];
                mma_tf32(O[ni], pa, b0, b1);
            }
        }
        // no trailing block sync: next tile writes the other K/V buffer;
        // safety follows from the sync at the top of the next iteration.
    }

    const float inv0 = 1.0f / l0, inv1 = 1.0f / l1;
    #pragma unroll
    for (int ni = 0; ni < 4; ni++) {
        int row = m0 + w16 + (lane >> 2);
        int col = h * DH + ni * 8 + 2 * (lane & 3);
        size_t off = ((size_t)(b * MM) + row) * DD + col;
        o[off]              = O[ni][0] * inv0;
        o[off + 1]          = O[ni][1] * inv0;
        o[off + 8 * DD]     = O[ni][2] * inv1;
        o[off + 8 * DD + 1] = O[ni][3] * inv1;
    }
}

// ---------------------------------------------------------------------------
// Column softmax over e + multiply:  ef = S * softmax_e(S)
// ---------------------------------------------------------------------------
__global__ __launch_bounds__(256) void col_softmax_mul(
    const float* __restrict__ S, float* __restrict__ ef)
{
    const int b  = blockIdx.y;
    const int d0 = blockIdx.x * 64;
    const int dx = threadIdx.x & 63, ry = threadIdx.x >> 6;
    const float* Sb = S  + (size_t)b * EE * DD + d0 + dx;
    float*       Eb = ef + (size_t)b * EE * DD + d0 + dx;

    __shared__ float red[4][64];

    float m = -1e30f;
    for (int e = ry; e < EE; e += 4) m = fmaxf(m, Sb[(size_t)e * DD]);
    red[ry][dx] = m;
    __syncthreads();
    m = fmaxf(fmaxf(red[0][dx], red[1][dx]), fmaxf(red[2][dx], red[3][dx]));
    __syncthreads();

    float s = 0.0f;
    for (int e = ry; e < EE; e += 4) s += __expf(Sb[(size_t)e * DD] - m);
    red[ry][dx] = s;
    __syncthreads();
    s = red[0][dx] + red[1][dx] + red[2][dx] + red[3][dx];
    float inv = 1.0f / s;

    for (int e = ry; e < EE; e += 4) {
        float v = Sb[(size_t)e * DD];
        Eb[(size_t)e * DD] = v * __expf(v - m) * inv;
    }
}

// ---------------------------------------------------------------------------
// LayerNorm (dim 256) + residual mix:  out = (1+alpha)*prev + (1-alpha)*LN(x)
// ---------------------------------------------------------------------------
__global__ __launch_bounds__(256) void ln_res(
    const float* __restrict__ ef2, const float* __restrict__ prev,
    const float* __restrict__ gamma, const float* __restrict__ beta,
    const float* __restrict__ alphap, float* __restrict__ out)
{
    const int row = blockIdx.x;
    const int c = threadIdx.x;
    const size_t off = (size_t)row * DD + c;

    float x = ef2[off];
    float s = x, q = x * x;
    #pragma unroll
    for (int o2 = 16; o2 > 0; o2 >>= 1) {
        s += __shfl_down_sync(0xFFFFFFFFu, s, o2);
        q += __shfl_down_sync(0xFFFFFFFFu, q, o2);
    }
    __shared__ float rs[8], rq[8], mv[2];
    int w = c >> 5, l = c & 31;
    if (l == 0) { rs[w] = s; rq[w] = q; }
    __syncthreads();
    if (c == 0) {
        float S2 = 0.0f, Q2 = 0.0f;
        #pragma unroll
        for (int i = 0; i < 8; i++) { S2 += rs[i]; Q2 += rq[i]; }
        float mean = S2 * (1.0f / 256.0f);
        float var  = Q2 * (1.0f / 256.0f) - mean * mean;
        mv[0] = mean;
        mv[1] = rsqrtf(var + 1e-5f);
    }
    __syncthreads();

    float n = (x - mv[0]) * mv[1] * gamma[c] + beta[c];
    float a = *alphap;
    float p = prev[off];
    out[off] = (1.0f + a) * p + (1.0f - a) * n;
}

// ---------------------------------------------------------------------------
// Launch
// ---------------------------------------------------------------------------
extern "C" void kernel_launch(void* const* d_in, const int* in_sizes, int n_in,
                              void* d_out, int out_size)
{
    const float* feat = (const float*)d_in[0];
    const float* inc  = (const float*)d_in[1];
    const float* prev = (const float*)d_in[2];
    const float* ipw  = (const float*)d_in[3];
    const float* ipb  = (const float*)d_in[4];
    const float* opw  = (const float*)d_in[5];
    const float* opb  = (const float*)d_in[6];
    const float* pw   = (const float*)d_in[7];
    const float* gam  = (const float*)d_in[8];
    const float* bet  = (const float*)d_in[9];
    const float* alp  = (const float*)d_in[10];
    float* out = (float*)d_out;

    float *qkv, *attn, *attnp, *Sp, *Sb, *ef, *ef2;
    cudaGetSymbolAddress((void**)&qkv,   g_qkv);
    cudaGetSymbolAddress((void**)&attn,  g_attn);
    cudaGetSymbolAddress((void**)&attnp, g_attnp);
    cudaGetSymbolAddress((void**)&Sp,    g_Sp);
    cudaGetSymbolAddress((void**)&Sb,    g_S);
    cudaGetSymbolAddress((void**)&ef,    g_ef);
    cudaGetSymbolAddress((void**)&ef2,   g_ef2);

    // 1. QKV projection: [8192,768] = feat @ ipw^T + b
    mm_nt128<<<dim3(TD / 64, (BB * MM) / 128), 256>>>(feat, ipw, ipb, qkv,
                                                      BB * MM, TD, DD);
    // 2. flash attention (128 q-rows per block)
    flash_tf32<<<dim3(MM / 128, BB * HH), 256>>>(qkv, attn);
    // 3. out projection: [8192,256]
    mm_nt64<<<dim3(DD / 64, (BB * MM) / 64), 128>>>(attn, opw, opb, attnp,
                                                    BB * MM, DD, DD);
    // 4. S = inc^T @ attnp  (split-K x4) + reduce
    mm_tn_S<<<dim3(EE / 64, DD / 64, BB * NSPLIT), 128>>>(inc, attnp, Sp);
    reduce_S<<<(BB * EE * DD / 4 + 255) / 256, 256>>>((const float4*)Sp,
                                                      (float4*)Sb);
    // 5. ef = S * softmax_e(S)
    col_softmax_mul<<<dim3(DD / 64, BB), 256>>>(Sb, ef);
    // 6. ef2 = ef @ proj_w^T: [4096,256]
    mm_nt64<<<dim3(DD / 64, (BB * EE) / 64), 128>>>(ef, pw, nullptr, ef2,
                                                    BB * EE, DD, DD);
    // 7. LayerNorm + residual mix
    ln_res<<<BB * EE, 256>>>(ef2, prev, gam, bet, alp, out);
}

// round 8
// speedup vs baseline: 3.5218x; 1.5381x over previous
#include <cuda_runtime.h>
#include <cuda_fp16.h>
#include <math.h>
#include <stdint.h>

// Problem constants
#define BB   4
#define MM   2048
#define DD   256
#define EE   1024
#define HH   8
#define DH   32
#define TD   768   // 3*DD

// ---------------------------------------------------------------------------
// Scratch (no cudaMalloc allowed)
// ---------------------------------------------------------------------------
__device__ float  g_qkv    [BB * MM * TD];      // 24 MB
__device__ float  g_attn   [BB * MM * DD];      // 8 MB
__device__ float  g_attnp  [BB * MM * DD];      // 8 MB
__device__ __half g_incTh  [BB * EE * MM];      // 16 MB (inc^T as fp16)
__device__ __half g_attnpTh[BB * DD * MM];      // 4 MB  (attnp^T as fp16)
__device__ float  g_Sp     [4 * BB * EE * DD];  // 16 MB (split-K partials)
__device__ float  g_S      [BB * EE * DD];      // 4 MB
__device__ float  g_ef     [BB * EE * DD];      // 4 MB
__device__ float  g_ef2    [BB * EE * DD];      // 4 MB

// ---------------------------------------------------------------------------
// Helpers
// ---------------------------------------------------------------------------
__device__ __forceinline__ uint32_t f2h2(float a, float b) {
    __half2 h = __floats2half2_rn(a, b);
    return *reinterpret_cast<uint32_t*>(&h);
}

__device__ __forceinline__ void mma_f16(float* c, const uint32_t* a,
                                        uint32_t b0, uint32_t b1) {
    asm volatile(
        "mma.sync.aligned.m16n8k16.row.col.f32.f16.f16.f32 "
        "{%0,%1,%2,%3}, {%4,%5,%6,%7}, {%8,%9}, {%0,%1,%2,%3};\n"
        : "+f"(c[0]), "+f"(c[1]), "+f"(c[2]), "+f"(c[3])
        : "r"(a[0]), "r"(a[1]), "r"(a[2]), "r"(a[3]), "r"(b0), "r"(b1));
}

__device__ __forceinline__ void ldsm2t(uint32_t& b0, uint32_t& b1,
                                       uint32_t addr) {
    asm volatile("ldmatrix.sync.aligned.m8n8.x2.trans.shared.b16 {%0,%1}, [%2];"
                 : "=r"(b0), "=r"(b1) : "r"(addr));
}

__device__ __forceinline__ uint32_t smem_u32(const void* p) {
    uint32_t a;
    asm("{ .reg .u64 t; cvta.to.shared.u64 t, %1; cvt.u32.u64 %0, t; }"
        : "=r"(a) : "l"(p));
    return a;
}

// ---------------------------------------------------------------------------
// fp16 NT GEMM: C[M,N] = A[M,K] @ B[N,K]^T (+bias), fp32 accumulate.
// BM=128, BK=32, BN template (64/128). 256 threads, 8 warps (4m x 2n).
// TA/TB = float (converted in staging) or __half (copied directly).
// Split-K via grid.z: z = bz*nsplit + sp; partial written to C + z*sCz.
// ---------------------------------------------------------------------------
template <int BN, typename TA, typename TB>
__global__ __launch_bounds__(256) void hgemm_nt(
    const TA* __restrict__ A, const TB* __restrict__ B,
    const float* __restrict__ bias, float* __restrict__ C,
    int K, int lda, int ldb, int ldc,
    int nsplit, long long sAb, long long sBb, long long sCz)
{
    constexpr int NF = BN / 16;          // n-frags per warp (warp n = BN/2)
    __shared__ uint32_t As[2][128][20];  // fp16 pairs, pitch 40 halves
    __shared__ uint32_t Bs[2][BN][20];

    const int tid = threadIdx.x, lane = tid & 31, wid = tid >> 5;
    const int wm = (wid >> 1) * 32, wn = (wid & 1) * (BN / 2);
    const int z = blockIdx.z, bz = z / nsplit, sp = z % nsplit;
    const TA* Ab = A + (size_t)bz * sAb + (size_t)sp * K;
    const TB* Bb = B + (size_t)bz * sBb + (size_t)sp * K;
    float* Cb = C + (size_t)z * sCz;
    const int m0 = blockIdx.y * 128, n0 = blockIdx.x * BN;

    // staging maps
    const int ar = tid >> 1, asg = (tid & 1) * 16;           // 16 halves
    constexpr int TPB = 256 / BN;                            // threads/B-row
    constexpr int BH  = 32 / TPB;                            // halves/thread
    const int br = tid / TPB, bsg = (tid % TPB) * BH;

    const TA* Aption = Ab + (size_t)(m0 + ar) * lda + asg;
    const TB* Bption = Bb + (size_t)(n0 + br) * ldb + bsg;

    float4 paf[4], pbf[4];
    uint4  pah[2], pbh[2];

    auto loadA = [&](int k0) {
        if constexpr (sizeof(TA) == 4) {
            const float* p = (const float*)Aption + k0;
            #pragma unroll
            for (int i = 0; i < 4; i++) paf[i] = *(const float4*)(p + i * 4);
        } else {
            const __half* p = (const __half*)Aption + k0;
            pah[0] = *(const uint4*)p;
            pah[1] = *(const uint4*)(p + 8);
        }
    };
    auto storeA = [&](int s) {
        uint32_t* d = &As[s][ar][(tid & 1) * 8];
        if constexpr (sizeof(TA) == 4) {
            #pragma unroll
            for (int i = 0; i < 4; i++) {
                d[2 * i]     = f2h2(paf[i].x, paf[i].y);
                d[2 * i + 1] = f2h2(paf[i].z, paf[i].w);
            }
        } else {
            *(uint4*)d = pah[0];
            *(uint4*)(d + 4) = pah[1];
        }
    };
    auto loadB = [&](int k0) {
        if constexpr (sizeof(TB) == 4) {
            const float* p = (const float*)Bption + k0;
            #pragma unroll
            for (int i = 0; i < BH / 4; i++) pbf[i] = *(const float4*)(p + i * 4);
        } else {
            const __half* p = (const __half*)Bption + k0;
            #pragma unroll
            for (int i = 0; i < BH / 8; i++) pbh[i] = *(const uint4*)(p + i * 8);
        }
    };
    auto storeB = [&](int s) {
        uint32_t* d = &Bs[s][br][(tid % TPB) * (BH / 2)];
        if constexpr (sizeof(TB) == 4) {
            #pragma unroll
            for (int i = 0; i < BH / 4; i++) {
                d[2 * i]     = f2h2(pbf[i].x, pbf[i].y);
                d[2 * i + 1] = f2h2(pbf[i].z, pbf[i].w);
            }
        } else {
            #pragma unroll
            for (int i = 0; i < BH / 8; i++) *(uint4*)(d + 4 * i) = pbh[i];
        }
    };

    float acc[2][NF][4] = {};
    loadA(0); loadB(0);

    const int nk = K >> 5;
    for (int t = 0; t < nk; t++) {
        const int s = t & 1;
        storeA(s); storeB(s);
        if (t + 1 < nk) { loadA((t + 1) * 32); loadB((t + 1) * 32); }
        __syncthreads();

        #pragma unroll
        for (int kk = 0; kk < 2; kk++) {
            uint32_t a[2][4];
            const int c = kk * 8 + (lane & 3);
            #pragma unroll
            for (int mi = 0; mi < 2; mi++) {
                const int r = wm + mi * 16 + (lane >> 2);
                a[mi][0] = As[s][r][c];     a[mi][1] = As[s][r + 8][c];
                a[mi][2] = As[s][r][c + 4]; a[mi][3] = As[s][r + 8][c + 4];
            }
            #pragma unroll
            for (int ni = 0; ni < NF; ni++) {
                const int n = wn + ni * 8 + (lane >> 2);
                uint32_t b0 = Bs[s][n][c], b1 = Bs[s][n][c + 4];
                #pragma unroll
                for (int mi = 0; mi < 2; mi++)
                    mma_f16(acc[mi][ni], a[mi], b0, b1);
            }
        }
    }

    #pragma unroll
    for (int mi = 0; mi < 2; mi++) {
        #pragma unroll
        for (int ni = 0; ni < NF; ni++) {
            const int r = m0 + wm + mi * 16 + (lane >> 2);
            const int c = n0 + wn + ni * 8 + 2 * (lane & 3);
            float b0 = bias ? bias[c] : 0.0f;
            float b1 = bias ? bias[c + 1] : 0.0f;
            *(float2*)&Cb[(size_t)r * ldc + c] =
                make_float2(acc[mi][ni][0] + b0, acc[mi][ni][1] + b1);
            *(float2*)&Cb[(size_t)(r + 8) * ldc + c] =
                make_float2(acc[mi][ni][2] + b0, acc[mi][ni][3] + b1);
        }
    }
}

// ---------------------------------------------------------------------------
// 32x32 tiled transpose with fp16 output: out[b][c][r] = half(in[b][r][c])
// ---------------------------------------------------------------------------
__global__ __launch_bounds__(256) void transpose_h(
    const float* __restrict__ in, __half* __restrict__ out, int rows, int cols)
{
    __shared__ float t[32][33];
    const int b = blockIdx.z;
    const float* ib = in  + (size_t)b * rows * cols;
    __half*      ob = out + (size_t)b * rows * cols;
    const int c0 = blockIdx.x * 32, r0 = blockIdx.y * 32;
    const int tx = threadIdx.x & 31, ty = threadIdx.x >> 5;
    #pragma unroll
    for (int j = 0; j < 32; j += 8)
        t[ty + j][tx] = ib[(size_t)(r0 + ty + j) * cols + c0 + tx];
    __syncthreads();
    #pragma unroll
    for (int j = 0; j < 32; j += 8)
        ob[(size_t)(c0 + ty + j) * rows + r0 + tx] = __float2half(t[tx][ty + j]);
}

// Reduce 4 split-K partials ordered [b][sp]: S[b] = sum_sp Sp[b*4+sp]
__global__ __launch_bounds__(256) void reduce4(
    const float4* __restrict__ Sp, float4* __restrict__ S)
{
    const size_t per = (size_t)EE * DD / 4;
    size_t i = (size_t)blockIdx.x * 256 + threadIdx.x;
    if (i >= (size_t)BB * per) return;
    size_t b = i / per, j = i - b * per;
    const float4* p = Sp + 4 * b * per + j;
    float4 a = p[0], x = p[per], y = p[2 * per], w = p[3 * per];
    float4 r;
    r.x = (a.x + x.x) + (y.x + w.x);
    r.y = (a.y + x.y) + (y.y + w.y);
    r.z = (a.z + x.z) + (y.z + w.z);
    r.w = (a.w + x.w) + (y.w + w.w);
    S[i] = r;
}

// ---------------------------------------------------------------------------
// Flash attention, fp16 mma (m16n8k16), fp32 softmax/accumulate.
// 128 q-rows per block, 256 threads / 8 warps (16 q-rows each), BN=64 keys.
// V B-fragments via ldmatrix.x2.trans.
// ---------------------------------------------------------------------------
__global__ __launch_bounds__(256) void flash_h(
    const float* __restrict__ qkv, float* __restrict__ o)
{
    __shared__ uint32_t Ks[2][64][20];   // [key][dh-pairs] fp16
    __shared__ uint32_t Vs[2][64][20];   // [key][dh-pairs] fp16
    __shared__ uint32_t Ps[128 * 36];    // [q-row][key-pairs] fp16; Q scratch

    const int bh = blockIdx.y;
    const int b = bh >> 3, h = bh & 7;
    const int m0 = blockIdx.x * 128;
    const int tid = threadIdx.x;
    const int lane = tid & 31;
    const int w16 = (tid >> 5) * 16;

    const float scale = 0.1767766952966369f;   // 1/sqrt(32)
    const size_t base = (size_t)(b * MM) * TD + h * DH;

    // ---- stage Q (scaled fp16) into Ps scratch (pitch 20 u32) ----
    {
        const int r = tid >> 1, sg = (tid & 1) * 8;
        const float* qp = &qkv[base + (size_t)(m0 + r) * TD + (tid & 1) * 16];
        #pragma unroll
        for (int i = 0; i < 4; i++) {
            float4 v = *(const float4*)&qp[i * 4];
            Ps[r * 20 + sg + 2 * i]     = f2h2(v.x * scale, v.y * scale);
            Ps[r * 20 + sg + 2 * i + 1] = f2h2(v.z * scale, v.w * scale);
        }
    }
    __syncthreads();
    uint32_t qa[2][4];
    #pragma unroll
    for (int kk = 0; kk < 2; kk++) {
        const int r = w16 + (lane >> 2), c = kk * 8 + (lane & 3);
        qa[kk][0] = Ps[r * 20 + c];           qa[kk][1] = Ps[(r + 8) * 20 + c];
        qa[kk][2] = Ps[r * 20 + c + 4];       qa[kk][3] = Ps[(r + 8) * 20 + c + 4];
    }
    __syncthreads();

    const uint32_t vsb = smem_u32(Vs);

    float O[4][4] = {};
    float mr0 = -1e30f, mr1 = -1e30f, l0 = 0.0f, l1 = 0.0f;

    // K/V staging: rk = key row (0..63), ck = dh col base (8 floats each)
    const int rk = tid >> 2, ck = (tid & 3) * 8;
    float4 kpr[2], vpr[2];
    {
        const float* kp = &qkv[base + (size_t)rk * TD + 256 + ck];
        kpr[0] = *(const float4*)&kp[0];
        kpr[1] = *(const float4*)&kp[4];
        vpr[0] = *(const float4*)&kp[256];
        vpr[1] = *(const float4*)&kp[260];
    }

    const int ntile = MM / 64;
    for (int t = 0; t < ntile; t++) {
        const int s = t & 1;
        {
            uint4 ku, vu;
            ku.x = f2h2(kpr[0].x, kpr[0].y); ku.y = f2h2(kpr[0].z, kpr[0].w);
            ku.z = f2h2(kpr[1].x, kpr[1].y); ku.w = f2h2(kpr[1].z, kpr[1].w);
            vu.x = f2h2(vpr[0].x, vpr[0].y); vu.y = f2h2(vpr[0].z, vpr[0].w);
            vu.z = f2h2(vpr[1].x, vpr[1].y); vu.w = f2h2(vpr[1].z, vpr[1].w);
            *(uint4*)&Ks[s][rk][(tid & 3) * 4] = ku;
            *(uint4*)&Vs[s][rk][(tid & 3) * 4] = vu;
        }
        if (t + 1 < ntile) {
            const float* kp = &qkv[base + (size_t)((t + 1) * 64 + rk) * TD + 256 + ck];
            kpr[0] = *(const float4*)&kp[0];
            kpr[1] = *(const float4*)&kp[4];
            vpr[0] = *(const float4*)&kp[256];
            vpr[1] = *(const float4*)&kp[260];
        }
        __syncthreads();

        // ---- S = Q @ K^T : 8 n-frags x 2 k16 ----
        float sa[8][4] = {};
        #pragma unroll
        for (int j = 0; j < 8; j++) {
            #pragma unroll
            for (int kk = 0; kk < 2; kk++) {
                const int c = kk * 8 + (lane & 3);
                uint32_t b0 = Ks[s][j * 8 + (lane >> 2)][c];
                uint32_t b1 = Ks[s][j * 8 + (lane >> 2)][c + 4];
                mma_f16(sa[j], qa[kk], b0, b1);
            }
        }

        // ---- online softmax (rows r0, r0+8) ----
        float mx0 = -1e30f, mx1 = -1e30f;
        #pragma unroll
        for (int j = 0; j < 8; j++) {
            mx0 = fmaxf(mx0, fmaxf(sa[j][0], sa[j][1]));
            mx1 = fmaxf(mx1, fmaxf(sa[j][2], sa[j][3]));
        }
        mx0 = fmaxf(mx0, __shfl_xor_sync(0xFFFFFFFFu, mx0, 1));
        mx0 = fmaxf(mx0, __shfl_xor_sync(0xFFFFFFFFu, mx0, 2));
        mx1 = fmaxf(mx1, __shfl_xor_sync(0xFFFFFFFFu, mx1, 1));
        mx1 = fmaxf(mx1, __shfl_xor_sync(0xFFFFFFFFu, mx1, 2));

        float mn0 = fmaxf(mr0, mx0), mn1 = fmaxf(mr1, mx1);
        float al0 = __expf(mr0 - mn0), al1 = __expf(mr1 - mn1);
        mr0 = mn0; mr1 = mn1;

        float s0 = 0.0f, s1 = 0.0f;
        const int pr = w16 + (lane >> 2);
        #pragma unroll
        for (int j = 0; j < 8; j++) {
            float p00 = __expf(sa[j][0] - mn0);
            float p01 = __expf(sa[j][1] - mn0);
            float p10 = __expf(sa[j][2] - mn1);
            float p11 = __expf(sa[j][3] - mn1);
            s0 += p00 + p01; s1 += p10 + p11;
            const int pc = j * 4 + (lane & 3);
            Ps[pr * 36 + pc]       = f2h2(p00, p01);
            Ps[(pr + 8) * 36 + pc] = f2h2(p10, p11);
        }
        s0 += __shfl_xor_sync(0xFFFFFFFFu, s0, 1);
        s0 += __shfl_xor_sync(0xFFFFFFFFu, s0, 2);
        s1 += __shfl_xor_sync(0xFFFFFFFFu, s1, 1);
        s1 += __shfl_xor_sync(0xFFFFFFFFu, s1, 2);
        l0 = l0 * al0 + s0;
        l1 = l1 * al1 + s1;
        #pragma unroll
        for (int ni = 0; ni < 4; ni++) {
            O[ni][0] *= al0; O[ni][1] *= al0;
            O[ni][2] *= al1; O[ni][3] *= al1;
        }
        __syncwarp();

        // ---- O += P @ V : 4 k16 chunks x 4 n-frags; V via ldmatrix.trans ----
        #pragma unroll
        for (int kc = 0; kc < 4; kc++) {
            uint32_t pa[4];
            const int c = kc * 8 + (lane & 3);
            pa[0] = Ps[pr * 36 + c];       pa[1] = Ps[(pr + 8) * 36 + c];
            pa[2] = Ps[pr * 36 + c + 4];   pa[3] = Ps[(pr + 8) * 36 + c + 4];
            const int vrow = kc * 16 + (lane & 15);
            #pragma unroll
            for (int ni = 0; ni < 4; ni++) {
                uint32_t addr = vsb + ((s * 64 + vrow) * 20 + ni * 4) * 4;
                uint32_t b0, b1;
                ldsm2t(b0, b1, addr);
                mma_f16(O[ni], pa, b0, b1);
            }
        }
        // next tile writes the other K/V buffer; top-of-loop sync protects it.
    }

    const float inv0 = 1.0f / l0, inv1 = 1.0f / l1;
    #pragma unroll
    for (int ni = 0; ni < 4; ni++) {
        const int row = m0 + w16 + (lane >> 2);
        const int col = h * DH + ni * 8 + 2 * (lane & 3);
        size_t off = ((size_t)(b * MM) + row) * DD + col;
        o[off]              = O[ni][0] * inv0;
        o[off + 1]          = O[ni][1] * inv0;
        o[off + 8 * DD]     = O[ni][2] * inv1;
        o[off + 8 * DD + 1] = O[ni][3] * inv1;
    }
}

// ---------------------------------------------------------------------------
// Column softmax over e + multiply:  ef = S * softmax_e(S)
// ---------------------------------------------------------------------------
__global__ __launch_bounds__(256) void col_softmax_mul(
    const float* __restrict__ S, float* __restrict__ ef)
{
    const int b  = blockIdx.y;
    const int d0 = blockIdx.x * 64;
    const int dx = threadIdx.x & 63, ry = threadIdx.x >> 6;
    const float* Sb = S  + (size_t)b * EE * DD + d0 + dx;
    float*       Eb = ef + (size_t)b * EE * DD + d0 + dx;

    __shared__ float red[4][64];

    float m = -1e30f;
    for (int e = ry; e < EE; e += 4) m = fmaxf(m, Sb[(size_t)e * DD]);
    red[ry][dx] = m;
    __syncthreads();
    m = fmaxf(fmaxf(red[0][dx], red[1][dx]), fmaxf(red[2][dx], red[3][dx]));
    __syncthreads();

    float s = 0.0f;
    for (int e = ry; e < EE; e += 4) s += __expf(Sb[(size_t)e * DD] - m);
    red[ry][dx] = s;
    __syncthreads();
    s = red[0][dx] + red[1][dx] + red[2][dx] + red[3][dx];
    float inv = 1.0f / s;

    for (int e = ry; e < EE; e += 4) {
        float v = Sb[(size_t)e * DD];
        Eb[(size_t)e * DD] = v * __expf(v - m) * inv;
    }
}

// ---------------------------------------------------------------------------
// LayerNorm (dim 256) + residual mix:  out = (1+alpha)*prev + (1-alpha)*LN(x)
// ---------------------------------------------------------------------------
__global__ __launch_bounds__(256) void ln_res(
    const float* __restrict__ ef2, const float* __restrict__ prev,
    const float* __restrict__ gamma, const float* __restrict__ beta,
    const float* __restrict__ alphap, float* __restrict__ out)
{
    const int row = blockIdx.x;
    const int c = threadIdx.x;
    const size_t off = (size_t)row * DD + c;

    float x = ef2[off];
    float s = x, q = x * x;
    #pragma unroll
    for (int o2 = 16; o2 > 0; o2 >>= 1) {
        s += __shfl_down_sync(0xFFFFFFFFu, s, o2);
        q += __shfl_down_sync(0xFFFFFFFFu, q, o2);
    }
    __shared__ float rs[8], rq[8], mv[2];
    int w = c >> 5, l = c & 31;
    if (l == 0) { rs[w] = s; rq[w] = q; }
    __syncthreads();
    if (c == 0) {
        float S2 = 0.0f, Q2 = 0.0f;
        #pragma unroll
        for (int i = 0; i < 8; i++) { S2 += rs[i]; Q2 += rq[i]; }
        float mean = S2 * (1.0f / 256.0f);
        float var  = Q2 * (1.0f / 256.0f) - mean * mean;
        mv[0] = mean;
        mv[1] = rsqrtf(var + 1e-5f);
    }
    __syncthreads();

    float n = (x - mv[0]) * mv[1] * gamma[c] + beta[c];
    float a = *alphap;
    float p = prev[off];
    out[off] = (1.0f + a) * p + (1.0f - a) * n;
}

// ---------------------------------------------------------------------------
// Launch
// ---------------------------------------------------------------------------
extern "C" void kernel_launch(void* const* d_in, const int* in_sizes, int n_in,
                              void* d_out, int out_size)
{
    const float* feat = (const float*)d_in[0];
    const float* inc  = (const float*)d_in[1];
    const float* prev = (const float*)d_in[2];
    const float* ipw  = (const float*)d_in[3];
    const float* ipb  = (const float*)d_in[4];
    const float* opw  = (const float*)d_in[5];
    const float* opb  = (const float*)d_in[6];
    const float* pw   = (const float*)d_in[7];
    const float* gam  = (const float*)d_in[8];
    const float* bet  = (const float*)d_in[9];
    const float* alp  = (const float*)d_in[10];
    float* out = (float*)d_out;

    float *qkv, *attn, *attnp, *Sp, *Sb, *ef, *ef2;
    __half *incTh, *attnpTh;
    cudaGetSymbolAddress((void**)&qkv,     g_qkv);
    cudaGetSymbolAddress((void**)&attn,    g_attn);
    cudaGetSymbolAddress((void**)&attnp,   g_attnp);
    cudaGetSymbolAddress((void**)&incTh,   g_incTh);
    cudaGetSymbolAddress((void**)&attnpTh, g_attnpTh);
    cudaGetSymbolAddress((void**)&Sp,      g_Sp);
    cudaGetSymbolAddress((void**)&Sb,      g_S);
    cudaGetSymbolAddress((void**)&ef,      g_ef);
    cudaGetSymbolAddress((void**)&ef2,     g_ef2);

    // 0. transpose+convert inc [b,m,e] -> incTh [b,e,m] fp16
    transpose_h<<<dim3(EE / 32, MM / 32, BB), 256>>>(inc, incTh, MM, EE);

    // 1. QKV projection: [8192,768] = feat @ ipw^T + b
    hgemm_nt<128, float, float>
        <<<dim3(TD / 128, (BB * MM) / 128, 1), 256>>>(
            feat, ipw, ipb, qkv, DD, DD, DD, TD, 1, 0, 0, 0);

    // 2. flash attention (fp16)
    flash_h<<<dim3(MM / 128, BB * HH), 256>>>(qkv, attn);

    // 3. out projection: [8192,256]
    hgemm_nt<64, float, float>
        <<<dim3(DD / 64, (BB * MM) / 128, 1), 256>>>(
            attn, opw, opb, attnp, DD, DD, DD, DD, 1, 0, 0, 0);

    // 3b. transpose+convert attnp [b,m,d] -> attnpTh [b,d,m] fp16
    transpose_h<<<dim3(DD / 32, MM / 32, BB), 256>>>(attnp, attnpTh, MM, DD);

    // 4. S = incTh @ attnpTh^T  (fp16 NT, split-K x4) + reduce
    hgemm_nt<128, __half, __half>
        <<<dim3(DD / 128, EE / 128, BB * 4), 256>>>(
            incTh, attnpTh, nullptr, Sp, MM / 4, MM, MM, DD,
            4, (long long)EE * MM, (long long)DD * MM, (long long)EE * DD);
    reduce4<<<(BB * EE * DD / 4 + 255) / 256, 256>>>((const float4*)Sp,
                                                     (float4*)Sb);

    // 5. ef = S * softmax_e(S)
    col_softmax_mul<<<dim3(DD / 64, BB), 256>>>(Sb, ef);

    // 6. ef2 = ef @ proj_w^T: [4096,256]
    hgemm_nt<64, float, float>
        <<<dim3(DD / 64, (BB * EE) / 128, 1), 256>>>(
            ef, pw, nullptr, ef2, DD, DD, DD, DD, 1, 0, 0, 0);

    // 7. LayerNorm + residual mix
    ln_res<<<BB * EE, 256>>>(ef2, prev, gam, bet, alp, out);
}

// round 10
// speedup vs baseline: 3.8156x; 1.0834x over previous
#include <cuda_runtime.h>
#include <cuda_fp16.h>
#include <math.h>
#include <stdint.h>

// Problem constants
#define BB   4
#define MM   2048
#define DD   256
#define EE   1024
#define HH   8
#define DH   32
#define TD   768   // 3*DD

// ---------------------------------------------------------------------------
// Scratch (no cudaMalloc allowed)
// ---------------------------------------------------------------------------
__device__ __half g_qkvh  [BB * MM * TD];      // 12 MB (Q pre-scaled)
__device__ __half g_attnh [BB * MM * DD];      // 4 MB
__device__ __half g_attnph[BB * MM * DD];      // 4 MB
__device__ float  g_Sp    [4 * BB * EE * DD];  // 16 MB (split-K partials)
__device__ float  g_S     [BB * EE * DD];      // 4 MB
__device__ float  g_ef    [BB * EE * DD];      // 4 MB
__device__ float  g_ef2   [BB * EE * DD];      // 4 MB

// ---------------------------------------------------------------------------
// Helpers
// ---------------------------------------------------------------------------
__device__ __forceinline__ uint32_t f2h2(float a, float b) {
    __half2 h = __floats2half2_rn(a, b);
    return *reinterpret_cast<uint32_t*>(&h);
}

__device__ __forceinline__ void mma_f16(float* c, const uint32_t* a,
                                        uint32_t b0, uint32_t b1) {
    asm volatile(
        "mma.sync.aligned.m16n8k16.row.col.f32.f16.f16.f32 "
        "{%0,%1,%2,%3}, {%4,%5,%6,%7}, {%8,%9}, {%0,%1,%2,%3};\n"
        : "+f"(c[0]), "+f"(c[1]), "+f"(c[2]), "+f"(c[3])
        : "r"(a[0]), "r"(a[1]), "r"(a[2]), "r"(a[3]), "r"(b0), "r"(b1));
}

__device__ __forceinline__ void ldsm2t(uint32_t& b0, uint32_t& b1,
                                       uint32_t addr) {
    asm volatile("ldmatrix.sync.aligned.m8n8.x2.trans.shared.b16 {%0,%1}, [%2];"
                 : "=r"(b0), "=r"(b1) : "r"(addr));
}

__device__ __forceinline__ void ldsm4t(uint32_t* a, uint32_t addr) {
    asm volatile("ldmatrix.sync.aligned.m8n8.x4.trans.shared.b16 {%0,%1,%2,%3}, [%4];"
                 : "=r"(a[0]), "=r"(a[1]), "=r"(a[2]), "=r"(a[3]) : "r"(addr));
}

__device__ __forceinline__ uint32_t smem_u32(const void* p) {
    uint32_t a;
    asm("{ .reg .u64 t; cvta.to.shared.u64 t, %1; cvt.u32.u64 %0, t; }"
        : "=r"(a) : "l"(p));
    return a;
}

// ---------------------------------------------------------------------------
// fp16 NT GEMM: C[M,N] = A[M,K] @ B[N,K]^T (+bias), fp32 accumulate.
// BM=128, BK=32, BN template. 256 threads, 8 warps (4m x 2n).
// TA = float (converted in staging) or __half. TC = float or __half.
// Columns c < scale_cols get multiplied by qs after bias (Q pre-scaling).
// ---------------------------------------------------------------------------
template <int BN, typename TA, typename TC>
__global__ __launch_bounds__(256) void hgemm_nt(
    const TA* __restrict__ A, const float* __restrict__ W,
    const float* __restrict__ bias, TC* __restrict__ C,
    int K, int lda, int ldc, int scale_cols, float qs)
{
    constexpr int NF = BN / 16;
    __shared__ uint32_t As[2][128][20];
    __shared__ uint32_t Bs[2][BN][20];

    const int tid = threadIdx.x, lane = tid & 31, wid = tid >> 5;
    const int wm = (wid >> 1) * 32, wn = (wid & 1) * (BN / 2);
    const int m0 = blockIdx.y * 128, n0 = blockIdx.x * BN;

    const int ar = tid >> 1, asg = (tid & 1) * 16;
    constexpr int TPB = 256 / BN;
    constexpr int BH  = 32 / TPB;
    const int br = tid / TPB, bsg = (tid % TPB) * BH;

    const TA* Ap = A + (size_t)(m0 + ar) * lda + asg;
    const float* Wp = W + (size_t)(n0 + br) * K + bsg;

    float4 paf[4], pbf[BH / 4];
    uint4  pah[2];

    auto loadA = [&](int k0) {
        if constexpr (sizeof(TA) == 4) {
            const float* p = (const float*)Ap + k0;
            #pragma unroll
            for (int i = 0; i < 4; i++) paf[i] = *(const float4*)(p + i * 4);
        } else {
            const __half* p = (const __half*)Ap + k0;
            pah[0] = *(const uint4*)p;
            pah[1] = *(const uint4*)(p + 8);
        }
    };
    auto storeA = [&](int s) {
        uint32_t* d = &As[s][ar][(tid & 1) * 8];
        if constexpr (sizeof(TA) == 4) {
            #pragma unroll
            for (int i = 0; i < 4; i++) {
                d[2 * i]     = f2h2(paf[i].x, paf[i].y);
                d[2 * i + 1] = f2h2(paf[i].z, paf[i].w);
            }
        } else {
            *(uint4*)d = pah[0];
            *(uint4*)(d + 4) = pah[1];
        }
    };
    auto loadB = [&](int k0) {
        const float* p = Wp + k0;
        #pragma unroll
        for (int i = 0; i < BH / 4; i++) pbf[i] = *(const float4*)(p + i * 4);
    };
    auto storeB = [&](int s) {
        uint32_t* d = &Bs[s][br][(tid % TPB) * (BH / 2)];
        #pragma unroll
        for (int i = 0; i < BH / 4; i++) {
            d[2 * i]     = f2h2(pbf[i].x, pbf[i].y);
            d[2 * i + 1] = f2h2(pbf[i].z, pbf[i].w);
        }
    };

    float acc[2][NF][4] = {};
    loadA(0); loadB(0);

    const int nk = K >> 5;
    for (int t = 0; t < nk; t++) {
        const int s = t & 1;
        storeA(s); storeB(s);
        if (t + 1 < nk) { loadA((t + 1) * 32); loadB((t + 1) * 32); }
        __syncthreads();

        #pragma unroll
        for (int kk = 0; kk < 2; kk++) {
            uint32_t a[2][4];
            const int c = kk * 8 + (lane & 3);
            #pragma unroll
            for (int mi = 0; mi < 2; mi++) {
                const int r = wm + mi * 16 + (lane >> 2);
                a[mi][0] = As[s][r][c];     a[mi][1] = As[s][r + 8][c];
                a[mi][2] = As[s][r][c + 4]; a[mi][3] = As[s][r + 8][c + 4];
            }
            #pragma unroll
            for (int ni = 0; ni < NF; ni++) {
                const int n = wn + ni * 8 + (lane >> 2);
                uint32_t b0 = Bs[s][n][c], b1 = Bs[s][n][c + 4];
                #pragma unroll
                for (int mi = 0; mi < 2; mi++)
                    mma_f16(acc[mi][ni], a[mi], b0, b1);
            }
        }
    }

    #pragma unroll
    for (int mi = 0; mi < 2; mi++) {
        #pragma unroll
        for (int ni = 0; ni < NF; ni++) {
            const int r = m0 + wm + mi * 16 + (lane >> 2);
            const int c = n0 + wn + ni * 8 + 2 * (lane & 3);
            float b0 = bias ? bias[c] : 0.0f;
            float b1 = bias ? bias[c + 1] : 0.0f;
            float v0 = acc[mi][ni][0] + b0, v1 = acc[mi][ni][1] + b1;
            float v2 = acc[mi][ni][2] + b0, v3 = acc[mi][ni][3] + b1;
            if (c < scale_cols) { v0 *= qs; v1 *= qs; v2 *= qs; v3 *= qs; }
            if constexpr (sizeof(TC) == 2) {
                *(__half2*)&C[(size_t)r * ldc + c]       = __floats2half2_rn(v0, v1);
                *(__half2*)&C[(size_t)(r + 8) * ldc + c] = __floats2half2_rn(v2, v3);
            } else {
                *(float2*)&C[(size_t)r * ldc + c]       = make_float2(v0, v1);
                *(float2*)&C[(size_t)(r + 8) * ldc + c] = make_float2(v2, v3);
            }
        }
    }
}

// ---------------------------------------------------------------------------
// fp16 TN GEMM (for S): Sp[z][e][d] = sum_m inc[b][m][e] * attnph[b][m][d]
// A = inc fp32 [m][e] (lda=EE), B = attnph fp16 [m][d] (ldb=DD), both m-major;
// fragments via ldmatrix.trans. BM=128(e), BN=64(d), BK=32(m), 256 thr.
// Split-K x4 over m: z = blockIdx.z, bz=z>>2, sp=z&3.
// ---------------------------------------------------------------------------
__global__ __launch_bounds__(256) void sgemm_tn_h(
    const float* __restrict__ inc, const __half* __restrict__ Bh,
    float* __restrict__ Sp)
{
    __shared__ uint32_t As[2][32][68];   // [m][e-pairs], pitch 68 u32
    __shared__ uint32_t Bs[2][32][36];   // [m][d-pairs], pitch 36 u32

    const int tid = threadIdx.x, lane = tid & 31, wid = tid >> 5;
    const int wm = (wid >> 1) * 32, wn = (wid & 1) * 32;
    const int z = blockIdx.z, bz = z >> 2, sp = z & 3;
    const int e0 = blockIdx.y * 128, d0 = blockIdx.x * 64;
    const float*  Ab = inc + (size_t)bz * MM * EE + (size_t)(sp * 512) * EE;
    const __half* Bb = Bh  + (size_t)bz * MM * DD + (size_t)(sp * 512) * DD;

    // staging: am/bm = m-row (0..31); A: 16 floats->halves, B: 8 halves
    const int am = tid >> 3, ac = (tid & 7) * 16;   // halves along e
    const float*  Apt = Ab + (size_t)am * EE + e0 + ac;
    const __half* Bpt = Bb + (size_t)am * DD + d0 + (tid & 7) * 8;

    float4 pa[4];
    uint4  pb;
    auto loadT = [&](int k0) {
        const float* p = Apt + (size_t)k0 * EE;
        #pragma unroll
        for (int i = 0; i < 4; i++) pa[i] = *(const float4*)(p + i * 4);
        pb = *(const uint4*)(Bpt + (size_t)k0 * DD);
    };
    auto storeT = [&](int s) {
        uint32_t* da = &As[s][am][(tid & 7) * 8];
        #pragma unroll
        for (int i = 0; i < 4; i++) {
            da[2 * i]     = f2h2(pa[i].x, pa[i].y);
            da[2 * i + 1] = f2h2(pa[i].z, pa[i].w);
        }
        *(uint4*)&Bs[s][am][(tid & 7) * 4] = pb;
    };

    const uint32_t asb = smem_u32(As), bsb = smem_u32(Bs);

    float acc[2][4][4] = {};
    loadT(0);

    for (int t = 0; t < 16; t++) {   // 512 / 32
        const int s = t & 1;
        storeT(s);
        if (t + 1 < 16) loadT((t + 1) * 32);
        __syncthreads();

        #pragma unroll
        for (int kk = 0; kk < 2; kk++) {
            uint32_t a[2][4];
            #pragma unroll
            for (int mi = 0; mi < 2; mi++) {
                const int mrow = kk * 16 + (lane & 7) + ((lane & 16) >> 1);
                const int ecol = wm + mi * 16 + (lane & 8);   // halves
                uint32_t addr = asb + (((s * 32 + mrow) * 68 + (ecol >> 1)) << 2);
                ldsm4t(a[mi], addr);
            }
            #pragma unroll
            for (int ni = 0; ni < 4; ni++) {
                const int mrow = kk * 16 + (lane & 15);
                uint32_t addr = bsb + (((s * 32 + mrow) * 36 + (wn >> 1) + ni * 4) << 2);
                uint32_t b0, b1;
                ldsm2t(b0, b1, addr);
                #pragma unroll
                for (int mi = 0; mi < 2; mi++)
                    mma_f16(acc[mi][ni], a[mi], b0, b1);
            }
        }
    }

    float* Sb = Sp + (size_t)z * EE * DD;
    #pragma unroll
    for (int mi = 0; mi < 2; mi++) {
        #pragma unroll
        for (int ni = 0; ni < 4; ni++) {
            const int e = e0 + wm + mi * 16 + (lane >> 2);
            const int d = d0 + wn + ni * 8 + 2 * (lane & 3);
            *(float2*)&Sb[(size_t)e * DD + d] =
                make_float2(acc[mi][ni][0], acc[mi][ni][1]);
            *(float2*)&Sb[(size_t)(e + 8) * DD + d] =
                make_float2(acc[mi][ni][2], acc[mi][ni][3]);
        }
    }
}

// Reduce 4 split-K partials ordered [b][sp]: S[b] = sum_sp Sp[b*4+sp]
__global__ __launch_bounds__(256) void reduce4(
    const float4* __restrict__ Sp, float4* __restrict__ S)
{
    const size_t per = (size_t)EE * DD / 4;
    size_t i = (size_t)blockIdx.x * 256 + threadIdx.x;
    if (i >= (size_t)BB * per) return;
    size_t b = i / per, j = i - b * per;
    const float4* p = Sp + 4 * b * per + j;
    float4 a = p[0], x = p[per], y = p[2 * per], w = p[3 * per];
    float4 r;
    r.x = (a.x + x.x) + (y.x + w.x);
    r.y = (a.y + x.y) + (y.y + w.y);
    r.z = (a.z + x.z) + (y.z + w.z);
    r.w = (a.w + x.w) + (y.w + w.w);
    S[i] = r;
}

// ---------------------------------------------------------------------------
// Flash attention, fp16 in/out. 128 q-rows per block, 256 threads / 8 warps.
// Q pre-scaled in QKV epilogue; staging = pure uint4 copies.
// ---------------------------------------------------------------------------
__global__ __launch_bounds__(256) void flash_h(
    const __half* __restrict__ qkv, __half* __restrict__ o)
{
    __shared__ uint32_t Ks[2][64][20];
    __shared__ uint32_t Vs[2][64][20];
    __shared__ uint32_t Ps[128 * 36];

    const int bh = blockIdx.y;
    const int b = bh >> 3, h = bh & 7;
    const int m0 = blockIdx.x * 128;
    const int tid = threadIdx.x;
    const int lane = tid & 31;
    const int w16 = (tid >> 5) * 16;

    const size_t base = (size_t)(b * MM) * TD + h * DH;

    // ---- stage Q (already scaled fp16) into Ps scratch (pitch 20 u32) ----
    {
        const int r = tid >> 1;
        const __half* qp = &qkv[base + (size_t)(m0 + r) * TD + (tid & 1) * 16];
        uint32_t* d = &Ps[r * 20 + (tid & 1) * 8];
        *(uint4*)d       = *(const uint4*)qp;
        *(uint4*)(d + 4) = *(const uint4*)(qp + 8);
    }
    __syncthreads();
    uint32_t qa[2][4];
    #pragma unroll
    for (int kk = 0; kk < 2; kk++) {
        const int r = w16 + (lane >> 2), c = kk * 8 + (lane & 3);
        qa[kk][0] = Ps[r * 20 + c];        qa[kk][1] = Ps[(r + 8) * 20 + c];
        qa[kk][2] = Ps[r * 20 + c + 4];    qa[kk][3] = Ps[(r + 8) * 20 + c + 4];
    }
    __syncthreads();

    const uint32_t vsb = smem_u32(Vs);

    float O[4][4] = {};
    float mr0 = -1e30f, mr1 = -1e30f, l0 = 0.0f, l1 = 0.0f;

    const int rk = tid >> 2, ck = (tid & 3) * 8;   // 8 halves per thread
    uint4 ku, vu;
    {
        const __half* kp = &qkv[base + (size_t)rk * TD + 256 + ck];
        ku = *(const uint4*)kp;
        vu = *(const uint4*)(kp + 256);
    }

    const int ntile = MM / 64;
    for (int t = 0; t < ntile; t++) {
        const int s = t & 1;
        *(uint4*)&Ks[s][rk][(tid & 3) * 4] = ku;
        *(uint4*)&Vs[s][rk][(tid & 3) * 4] = vu;
        if (t + 1 < ntile) {
            const __half* kp = &qkv[base + (size_t)((t + 1) * 64 + rk) * TD + 256 + ck];
            ku = *(const uint4*)kp;
            vu = *(const uint4*)(kp + 256);
        }
        __syncthreads();

        // ---- S = Q @ K^T ----
        float sa[8][4] = {};
        #pragma unroll
        for (int j = 0; j < 8; j++) {
            #pragma unroll
            for (int kk = 0; kk < 2; kk++) {
                const int c = kk * 8 + (lane & 3);
                uint32_t b0 = Ks[s][j * 8 + (lane >> 2)][c];
                uint32_t b1 = Ks[s][j * 8 + (lane >> 2)][c + 4];
                mma_f16(sa[j], qa[kk], b0, b1);
            }
        }

        // ---- online softmax ----
        float mx0 = -1e30f, mx1 = -1e30f;
        #pragma unroll
        for (int j = 0; j < 8; j++) {
            mx0 = fmaxf(mx0, fmaxf(sa[j][0], sa[j][1]));
            mx1 = fmaxf(mx1, fmaxf(sa[j][2], sa[j][3]));
        }
        mx0 = fmaxf(mx0, __shfl_xor_sync(0xFFFFFFFFu, mx0, 1));
        mx0 = fmaxf(mx0, __shfl_xor_sync(0xFFFFFFFFu, mx0, 2));
        mx1 = fmaxf(mx1, __shfl_xor_sync(0xFFFFFFFFu, mx1, 1));
        mx1 = fmaxf(mx1, __shfl_xor_sync(0xFFFFFFFFu, mx1, 2));

        float mn0 = fmaxf(mr0, mx0), mn1 = fmaxf(mr1, mx1);
        float al0 = __expf(mr0 - mn0), al1 = __expf(mr1 - mn1);
        mr0 = mn0; mr1 = mn1;

        float s0 = 0.0f, s1 = 0.0f;
        const int pr = w16 + (lane >> 2);
        #pragma unroll
        for (int j = 0; j < 8; j++) {
            float p00 = __expf(sa[j][0] - mn0);
            float p01 = __expf(sa[j][1] - mn0);
            float p10 = __expf(sa[j][2] - mn1);
            float p11 = __expf(sa[j][3] - mn1);
            s0 += p00 + p01; s1 += p10 + p11;
            const int pc = j * 4 + (lane & 3);
            Ps[pr * 36 + pc]       = f2h2(p00, p01);
            Ps[(pr + 8) * 36 + pc] = f2h2(p10, p11);
        }
        s0 += __shfl_xor_sync(0xFFFFFFFFu, s0, 1);
        s0 += __shfl_xor_sync(0xFFFFFFFFu, s0, 2);
        s1 += __shfl_xor_sync(0xFFFFFFFFu, s1, 1);
        s1 += __shfl_xor_sync(0xFFFFFFFFu, s1, 2);
        l0 = l0 * al0 + s0;
        l1 = l1 * al1 + s1;
        #pragma unroll
        for (int ni = 0; ni < 4; ni++) {
            O[ni][0] *= al0; O[ni][1] *= al0;
            O[ni][2] *= al1; O[ni][3] *= al1;
        }
        __syncwarp();

        // ---- O += P @ V ----
        #pragma unroll
        for (int kc = 0; kc < 4; kc++) {
            uint32_t pa[4];
            const int c = kc * 8 + (lane & 3);
            pa[0] = Ps[pr * 36 + c];       pa[1] = Ps[(pr + 8) * 36 + c];
            pa[2] = Ps[pr * 36 + c + 4];   pa[3] = Ps[(pr + 8) * 36 + c + 4];
            const int vrow = kc * 16 + (lane & 15);
            #pragma unroll
            for (int ni = 0; ni < 4; ni++) {
                uint32_t addr = vsb + ((s * 64 + vrow) * 20 + ni * 4) * 4;
                uint32_t b0, b1;
                ldsm2t(b0, b1, addr);
                mma_f16(O[ni], pa, b0, b1);
            }
        }
    }

    const float inv0 = 1.0f / l0, inv1 = 1.0f / l1;
    #pragma unroll
    for (int ni = 0; ni < 4; ni++) {
        const int row = m0 + w16 + (lane >> 2);
        const int col = h * DH + ni * 8 + 2 * (lane & 3);
        size_t off = ((size_t)(b * MM) + row) * DD + col;
        *(__half2*)&o[off] = __floats2half2_rn(O[ni][0] * inv0, O[ni][1] * inv0);
        *(__half2*)&o[off + 8 * DD] =
            __floats2half2_rn(O[ni][2] * inv1, O[ni][3] * inv1);
    }
}

// ---------------------------------------------------------------------------
// Column softmax over e + multiply:  ef = S * softmax_e(S)
// ---------------------------------------------------------------------------
__global__ __launch_bounds__(256) void col_softmax_mul(
    const float* __restrict__ S, float* __restrict__ ef)
{
    const int b  = blockIdx.y;
    const int d0 = blockIdx.x * 64;
    const int dx = threadIdx.x & 63, ry = threadIdx.x >> 6;
    const float* Sb = S  + (size_t)b * EE * DD + d0 + dx;
    float*       Eb = ef + (size_t)b * EE * DD + d0 + dx;

    __shared__ float red[4][64];

    float m = -1e30f;
    for (int e = ry; e < EE; e += 4) m = fmaxf(m, Sb[(size_t)e * DD]);
    red[ry][dx] = m;
    __syncthreads();
    m = fmaxf(fmaxf(red[0][dx], red[1][dx]), fmaxf(red[2][dx], red[3][dx]));
    __syncthreads();

    float s = 0.0f;
    for (int e = ry; e < EE; e += 4) s += __expf(Sb[(size_t)e * DD] - m);
    red[ry][dx] = s;
    __syncthreads();
    s = red[0][dx] + red[1][dx] + red[2][dx] + red[3][dx];
    float inv = 1.0f / s;

    for (int e = ry; e < EE; e += 4) {
        float v = Sb[(size_t)e * DD];
        Eb[(size_t)e * DD] = v * __expf(v - m) * inv;
    }
}

// ---------------------------------------------------------------------------
// LayerNorm (dim 256) + residual mix:  out = (1+alpha)*prev + (1-alpha)*LN(x)
// ---------------------------------------------------------------------------
__global__ __launch_bounds__(256) void ln_res(
    const float* __restrict__ ef2, const float* __restrict__ prev,
    const float* __restrict__ gamma, const float* __restrict__ beta,
    const float* __restrict__ alphap, float* __restrict__ out)
{
    const int row = blockIdx.x;
    const int c = threadIdx.x;
    const size_t off = (size_t)row * DD + c;

    float x = ef2[off];
    float s = x, q = x * x;
    #pragma unroll
    for (int o2 = 16; o2 > 0; o2 >>= 1) {
        s += __shfl_down_sync(0xFFFFFFFFu, s, o2);
        q += __shfl_down_sync(0xFFFFFFFFu, q, o2);
    }
    __shared__ float rs[8], rq[8], mv[2];
    int w = c >> 5, l = c & 31;
    if (l == 0) { rs[w] = s; rq[w] = q; }
    __syncthreads();
    if (c == 0) {
        float S2 = 0.0f, Q2 = 0.0f;
        #pragma unroll
        for (int i = 0; i < 8; i++) { S2 += rs[i]; Q2 += rq[i]; }
        float mean = S2 * (1.0f / 256.0f);
        float var  = Q2 * (1.0f / 256.0f) - mean * mean;
        mv[0] = mean;
        mv[1] = rsqrtf(var + 1e-5f);
    }
    __syncthreads();

    float n = (x - mv[0]) * mv[1] * gamma[c] + beta[c];
    float a = *alphap;
    float p = prev[off];
    out[off] = (1.0f + a) * p + (1.0f - a) * n;
}

// ---------------------------------------------------------------------------
// Launch
// ---------------------------------------------------------------------------
extern "C" void kernel_launch(void* const* d_in, const int* in_sizes, int n_in,
                              void* d_out, int out_size)
{
    const float* feat = (const float*)d_in[0];
    const float* inc  = (const float*)d_in[1];
    const float* prev = (const float*)d_in[2];
    const float* ipw  = (const float*)d_in[3];
    const float* ipb  = (const float*)d_in[4];
    const float* opw  = (const float*)d_in[5];
    const float* opb  = (const float*)d_in[6];
    const float* pw   = (const float*)d_in[7];
    const float* gam  = (const float*)d_in[8];
    const float* bet  = (const float*)d_in[9];
    const float* alp  = (const float*)d_in[10];
    float* out = (float*)d_out;

    __half *qkvh, *attnh, *attnph;
    float *Sp, *Sb, *ef, *ef2;
    cudaGetSymbolAddress((void**)&qkvh,   g_qkvh);
    cudaGetSymbolAddress((void**)&attnh,  g_attnh);
    cudaGetSymbolAddress((void**)&attnph, g_attnph);
    cudaGetSymbolAddress((void**)&Sp,     g_Sp);
    cudaGetSymbolAddress((void**)&Sb,     g_S);
    cudaGetSymbolAddress((void**)&ef,     g_ef);
    cudaGetSymbolAddress((void**)&ef2,    g_ef2);

    const float qscale = 0.1767766952966369f;   // 1/sqrt(32)

    // 1. QKV projection -> fp16, Q third pre-scaled
    hgemm_nt<128, float, __half>
        <<<dim3(TD / 128, (BB * MM) / 128), 256>>>(
            feat, ipw, ipb, qkvh, DD, DD, TD, DD, qscale);

    // 2. flash attention (fp16 in/out)
    flash_h<<<dim3(MM / 128, BB * HH), 256>>>(qkvh, attnh);

    // 3. out projection -> fp16 attnph
    hgemm_nt<64, __half, __half>
        <<<dim3(DD / 64, (BB * MM) / 128), 256>>>(
            attnh, opw, opb, attnph, DD, DD, DD, 0, 1.0f);

    // 4. S = inc^T @ attnph  (TN fp16, ldmatrix.trans, split-K x4) + reduce
    sgemm_tn_h<<<dim3(DD / 64, EE / 128, BB * 4), 256>>>(inc, attnph, Sp);
    reduce4<<<(BB * EE * DD / 4 + 255) / 256, 256>>>((const float4*)Sp,
                                                     (float4*)Sb);

    // 5. ef = S * softmax_e(S)
    col_softmax_mul<<<dim3(DD / 64, BB), 256>>>(Sb, ef);

    // 6. ef2 = ef @ proj_w^T
    hgemm_nt<64, float, float>
        <<<dim3(DD / 64, (BB * EE) / 128), 256>>>(
            ef, pw, nullptr, ef2, DD, DD, DD, 0, 1.0f);

    // 7. LayerNorm + residual mix
    ln_res<<<BB * EE, 256>>>(ef2, prev, gam, bet, alp, out);
}